// round 3
// baseline (speedup 1.0000x reference)
#include <cuda_runtime.h>
#include <math.h>

#define TT 512
#define BB 64
#define EE 256
#define HH 200
#define G4 800
#define CC 20
#define NBD 50   // blocks per direction in LSTM kernel
#define HSL 4    // h-units per block (HH / NBD)

typedef unsigned long long ull;

// ---------------- device scratch (no allocations allowed) ----------------
__device__ float d_x[TT * BB * EE];            // LN'd embeddings, [tok=t*64+b][e]
__device__ float d_G[2 * TT * G4 * BB];        // gates_x [dir][t][gate_row][b]
__device__ float d_hall[TT * BB * 2 * HH];     // h states [t][b][dir*H + j]
__device__ float d_hbuf[2 * 2 * HH * BB];      // h double buffer [dir][phase][j][b]
__device__ float d_logits[BB * TT * CC];       // log_softmax outputs [b][t][c]
__device__ float d_loss[BB];
__device__ unsigned d_bar[2];                  // per-direction phase-count barrier

// packed f32x2 FMA (SASS FFMA2 — only reachable via PTX)
__device__ __forceinline__ ull ffma2(ull a, ull b, ull c) {
    ull d;
    asm("fma.rn.f32x2 %0, %1, %2, %3;" : "=l"(d) : "l"(a), "l"(b), "l"(c));
    return d;
}
__device__ __forceinline__ float2 unpack2(ull v) {
    float2 r;
    asm("mov.b64 {%0, %1}, %2;" : "=f"(r.x), "=f"(r.y) : "l"(v));
    return r;
}

__device__ __forceinline__ float sigf(float x)  { return 1.f / (1.f + __expf(-x)); }
__device__ __forceinline__ float tanhfast(float x) { return 1.f - 2.f / (__expf(2.f * x) + 1.f); }

// ---------------- K0: init ----------------
__global__ void k0_init() {
    int tid = threadIdx.x;
    for (int i = tid; i < 2 * 2 * HH * BB; i += 256) d_hbuf[i] = 0.f;
    if (tid < 2) d_bar[tid] = 0u;
}

// ---------------- K1: embedding + LayerNorm (warp per token) ----------------
__global__ void __launch_bounds__(256) k1_embed_ln(
    const int* __restrict__ words, const float* __restrict__ embed,
    const float* __restrict__ gamma, const float* __restrict__ beta)
{
    int wid = threadIdx.x >> 5, lane = threadIdx.x & 31;
    int tok = blockIdx.x * 8 + wid;          // tok = t*64 + b
    int t = tok >> 6, b = tok & 63;
    int word = words[b * TT + t];
    const float4* src = (const float4*)(embed + (size_t)word * EE);
    float4 v0 = src[lane * 2], v1 = src[lane * 2 + 1];
    float s = v0.x + v0.y + v0.z + v0.w + v1.x + v1.y + v1.z + v1.w;
    float q = v0.x*v0.x + v0.y*v0.y + v0.z*v0.z + v0.w*v0.w
            + v1.x*v1.x + v1.y*v1.y + v1.z*v1.z + v1.w*v1.w;
    #pragma unroll
    for (int o = 16; o; o >>= 1) {
        s += __shfl_xor_sync(~0u, s, o);
        q += __shfl_xor_sync(~0u, q, o);
    }
    float mu  = s * (1.f / EE);
    float var = q * (1.f / EE) - mu * mu;
    float rs  = rsqrtf(var + 1e-5f);
    const float4* g4 = (const float4*)gamma;
    const float4* bt4 = (const float4*)beta;
    float4 ga = g4[lane*2], gb = g4[lane*2+1];
    float4 ba = bt4[lane*2], bb = bt4[lane*2+1];
    float4 o0, o1;
    o0.x = (v0.x-mu)*rs*ga.x + ba.x;  o0.y = (v0.y-mu)*rs*ga.y + ba.y;
    o0.z = (v0.z-mu)*rs*ga.z + ba.z;  o0.w = (v0.w-mu)*rs*ga.w + ba.w;
    o1.x = (v1.x-mu)*rs*gb.x + bb.x;  o1.y = (v1.y-mu)*rs*gb.y + bb.y;
    o1.z = (v1.z-mu)*rs*gb.z + bb.z;  o1.w = (v1.w-mu)*rs*gb.w + bb.w;
    float4* dst = (float4*)(d_x + (size_t)tok * EE);
    dst[lane*2] = o0; dst[lane*2+1] = o1;
}

// ---------------- K2: SGEMM gates_x = X @ W_ih^T + b, both dirs fused ----------------
// C[32768, 1600], BM=128, BN=64, BK=8, 256 threads, 8x4 microtile, packed f32x2.
__global__ void __launch_bounds__(256) k2_gemm(
    const float* __restrict__ wihf, const float* __restrict__ wihb,
    const float* __restrict__ bf,   const float* __restrict__ bbias)
{
    __shared__ float2 AsD[8][128];   // duplicated (a,a) pairs: 8KB
    __shared__ float  Bs[8][64];
    int m0 = blockIdx.y * 128, n0 = blockIdx.x * 64;
    int tid = threadIdx.x;
    int ar = tid >> 1, ak = (tid & 1) * 4;
    int br = tid >> 2, bk = (tid & 3) * 2;
    int n_b = n0 + br;
    const float* wrow = (n_b < G4) ? (wihf + (size_t)n_b * EE)
                                   : (wihb + (size_t)(n_b - G4) * EE);
    int rmt = tid & 15, cmt = tid >> 4;

    ull acc2[8][2];
    #pragma unroll
    for (int i = 0; i < 8; ++i) { acc2[i][0] = 0ull; acc2[i][1] = 0ull; }

    for (int k0 = 0; k0 < EE; k0 += 8) {
        float4 av = *(const float4*)(d_x + (size_t)(m0 + ar) * EE + k0 + ak);
        float2 bv = *(const float2*)(wrow + k0 + bk);
        __syncthreads();
        AsD[ak+0][ar] = make_float2(av.x, av.x);
        AsD[ak+1][ar] = make_float2(av.y, av.y);
        AsD[ak+2][ar] = make_float2(av.z, av.z);
        AsD[ak+3][ar] = make_float2(av.w, av.w);
        Bs[bk][br] = bv.x; Bs[bk+1][br] = bv.y;
        __syncthreads();
        #pragma unroll
        for (int kk = 0; kk < 8; ++kk) {
            ull bp0 = *(const ull*)&Bs[kk][cmt * 4];
            ull bp1 = *(const ull*)&Bs[kk][cmt * 4 + 2];
            #pragma unroll
            for (int i = 0; i < 8; ++i) {
                ull ad = *(const ull*)&AsD[kk][rmt + 16 * i];
                acc2[i][0] = ffma2(ad, bp0, acc2[i][0]);
                acc2[i][1] = ffma2(ad, bp1, acc2[i][1]);
            }
        }
    }
    #pragma unroll
    for (int q = 0; q < 2; ++q) {
        #pragma unroll
        for (int jj = 0; jj < 2; ++jj) {
            int n = n0 + cmt * 4 + 2 * q + jj;
            int dir = (n >= G4) ? 1 : 0;
            int r = n - dir * G4;
            float bias = dir ? bbias[r] : bf[r];
            float* Gp = d_G + (size_t)dir * (TT * G4 * BB);
            #pragma unroll
            for (int i = 0; i < 8; ++i) {
                float2 v = unpack2(acc2[i][q]);
                float val = jj ? v.y : v.x;
                int m = m0 + rmt + 16 * i;
                int t = m >> 6, b = m & 63;
                Gp[((size_t)t * G4 + r) * BB + b] = val + bias;
            }
        }
    }
}

// ---------------- K3: persistent bidirectional LSTM with grid barrier ----------------
// Grid = 100 blocks (50 per direction), 128 threads, all resident. Packed f32x2 FMA.
__global__ void __launch_bounds__(128, 1) k3_lstm(
    const float* __restrict__ whhf, const float* __restrict__ whhb,
    const int* __restrict__ seq_len)
{
    extern __shared__ float hsh[];        // [HH][BB] = 51200 B, transposed h_prev
    __shared__ float2 wsh2[16 * HH];      // duplicated (w,w): 25600 B
    __shared__ float  gsh[16 * BB];       // gate staging
    __shared__ float  csh[HSL * BB];      // cell state slice
    __shared__ int    lensh[BB];

    int tid = threadIdx.x;
    int dir = blockIdx.x / NBD;
    int sl  = blockIdx.x % NBD;
    int j0  = sl * HSL;
    const float* whh = dir ? whhb : whhf;

    for (int i = tid; i < 16 * HH; i += 128) {
        int rr = i / HH, k = i % HH;
        int rglob = (rr >> 2) * HH + j0 + (rr & 3);   // gate q = rr>>2, unit = rr&3
        float w = whh[(size_t)rglob * HH + k];
        wsh2[i] = make_float2(w, w);
    }
    if (tid < BB) lensh[tid] = seq_len[tid];
    csh[tid] = 0.f; csh[tid + 128] = 0.f;

    const float* G = d_G + (size_t)dir * (TT * G4 * BB);
    float* hb = d_hbuf + dir * (2 * HH * BB);

    int bg = tid & 15, rg = tid >> 4;
    int b0 = bg * 4;
    int rr0 = rg * 2, rr1 = rr0 + 1;
    int r0g = (rr0 >> 2) * HH + j0 + (rr0 & 3);
    int r1g = (rr1 >> 2) * HH + j0 + (rr1 & 3);
    __syncthreads();

    for (int st = 0; st < TT; ++st) {
        int t = dir ? (TT - 1 - st) : st;
        int p = st & 1;

        // prefetch this step's gx (independent of h load below)
        ulonglong2 g0 = *(const ulonglong2*)(G + ((size_t)t * G4 + r0g) * BB + b0);
        ulonglong2 g1 = *(const ulonglong2*)(G + ((size_t)t * G4 + r1g) * BB + b0);

        // h_prev (phase p) from L2 into shared
        {
            const float4* src = (const float4*)(hb + p * (HH * BB));
            float4* dst = (float4*)hsh;
            for (int i = tid; i < HH * BB / 4; i += 128) dst[i] = __ldcg(src + i);
        }
        __syncthreads();

        // gates = gx + Whh_slice @ h_prev   (2 rows x 4 batches per thread)
        ull a0lo = g0.x, a0hi = g0.y, a1lo = g1.x, a1hi = g1.y;
        const float2* w0 = wsh2 + rr0 * HH;
        const float2* w1 = wsh2 + rr1 * HH;
        #pragma unroll 4
        for (int k = 0; k < HH; ++k) {
            ulonglong2 hv = *(const ulonglong2*)(hsh + k * BB + b0);
            ull w0p = *(const ull*)(w0 + k);
            ull w1p = *(const ull*)(w1 + k);
            a0lo = ffma2(w0p, hv.x, a0lo);
            a0hi = ffma2(w0p, hv.y, a0hi);
            a1lo = ffma2(w1p, hv.x, a1lo);
            a1hi = ffma2(w1p, hv.y, a1hi);
        }
        *(ulonglong2*)(gsh + rr0 * BB + b0) = make_ulonglong2(a0lo, a0hi);
        *(ulonglong2*)(gsh + rr1 * BB + b0) = make_ulonglong2(a1lo, a1hi);
        __syncthreads();

        // cell/hidden update: 4 h-units x 64 batches
        #pragma unroll
        for (int u = 0; u < 2; ++u) {
            int idx = tid + u * 128;
            int jj = idx >> 6, b = idx & 63;
            float gi = gsh[jj * BB + b];
            float gf = gsh[(4 + jj) * BB + b];
            float gg = gsh[(8 + jj) * BB + b];
            float go = gsh[(12 + jj) * BB + b];
            float c  = csh[jj * BB + b];
            float cn = sigf(gf) * c + sigf(gi) * tanhfast(gg);
            float hn = sigf(go) * tanhfast(cn);
            bool valid = (t < lensh[b]);
            float hold = hsh[(j0 + jj) * BB + b];
            float ho = valid ? hn : hold;
            float co = valid ? cn : c;
            csh[jj * BB + b] = co;
            __stcg(hb + (p ^ 1) * (HH * BB) + (j0 + jj) * BB + b, ho);
            d_hall[((size_t)t * BB + b) * (2 * HH) + dir * HH + j0 + jj] = ho;
        }

        // per-direction grid barrier (monotone phase counter; reset by K0)
        __threadfence();
        __syncthreads();
        if (tid == 0) {
            atomicAdd(&d_bar[dir], 1u);
            unsigned tgt = (unsigned)(st + 1) * NBD;
            while (*((volatile unsigned*)&d_bar[dir]) < tgt) { }
            __threadfence();
        }
        __syncthreads();
    }
}

// ---------------- K4: FC + log_softmax (warp per token) ----------------
__global__ void __launch_bounds__(128) k4_fc(
    const float* __restrict__ fcw, const float* __restrict__ fcb)
{
    __shared__ float wsh[CC * 401];   // pad 401 -> conflict-free column reads
    __shared__ float fbsh[CC];
    __shared__ float hs4[4][2 * HH];
    int tid = threadIdx.x;
    for (int i = tid; i < CC * 2 * HH; i += 128) {
        int c = i / (2 * HH), k = i % (2 * HH);
        wsh[c * 401 + k] = fcw[i];
    }
    if (tid < CC) fbsh[tid] = fcb[tid];
    __syncthreads();

    int w = tid >> 5, lane = tid & 31;
    int tok = blockIdx.x * 4 + w;                    // tok = t*64 + b
    for (int k = lane; k < 2 * HH; k += 32) hs4[w][k] = d_hall[(size_t)tok * (2 * HH) + k];
    __syncwarp();

    float acc = -1e30f;
    if (lane < CC) {
        acc = fbsh[lane];
        const float* wr = wsh + lane * 401;
        #pragma unroll 4
        for (int k = 0; k < 2 * HH; ++k) acc += hs4[w][k] * wr[k];
    }
    float m = acc;
    #pragma unroll
    for (int o = 16; o; o >>= 1) m = fmaxf(m, __shfl_xor_sync(~0u, m, o));
    float e = (lane < CC) ? __expf(acc - m) : 0.f;
    #pragma unroll
    for (int o = 16; o; o >>= 1) e += __shfl_xor_sync(~0u, e, o);
    float lse = m + __logf(e);
    if (lane < CC) {
        int t = tok >> 6, b = tok & 63;
        d_logits[((size_t)b * TT + t) * CC + lane] = acc - lse;
    }
}

// ---------------- K5: CRF NLL, one warp per batch element ----------------
__global__ void __launch_bounds__(32) k5_crf(
    const int* __restrict__ seq_len, const int* __restrict__ target,
    const float* __restrict__ trans, const float* __restrict__ start,
    const float* __restrict__ endsc)
{
    int b = blockIdx.x;
    int lane = threadIdx.x;
    int c = (lane < CC) ? lane : 0;
    int len = seq_len[b];
    const float* L = d_logits + (size_t)b * TT * CC;
    const int* tg = target + (size_t)b * TT;

    float tcol[CC];
    #pragma unroll
    for (int i = 0; i < CC; ++i) tcol[i] = (lane < CC) ? trans[i * CC + c] : 0.f;

    float alpha = (lane < CC) ? (start[c] + L[c]) : -1e30f;

    for (int t = 1; t < len; ++t) {
        float va[CC];
        #pragma unroll
        for (int i = 0; i < CC; ++i)
            va[i] = __shfl_sync(~0u, alpha, i) + tcol[i];
        float m = va[0];
        #pragma unroll
        for (int i = 1; i < CC; ++i) m = fmaxf(m, va[i]);
        float s = 0.f;
        #pragma unroll
        for (int i = 0; i < CC; ++i) s += __expf(va[i] - m);
        float emit = (lane < CC) ? L[t * CC + c] : 0.f;
        float nw = m + __logf(s) + emit;
        alpha = (lane < CC) ? nw : -1e30f;
    }

    // logZ = lse(alpha + end)
    float v = (lane < CC) ? (alpha + endsc[c]) : -1e30f;
    float m = v;
    #pragma unroll
    for (int o = 16; o; o >>= 1) m = fmaxf(m, __shfl_xor_sync(~0u, m, o));
    float s = __expf(v - m);
    if (lane >= CC) s = 0.f;
    #pragma unroll
    for (int o = 16; o; o >>= 1) s += __shfl_xor_sync(~0u, s, o);
    float logZ = m + __logf(s);

    // gold score
    float es = 0.f;
    for (int t = lane; t < len; t += 32) es += L[t * CC + tg[t]];
    float ts = 0.f;
    for (int t = lane; t < len - 1; t += 32) ts += trans[tg[t] * CC + tg[t + 1]];
    float g = es + ts;
    #pragma unroll
    for (int o = 16; o; o >>= 1) g += __shfl_xor_sync(~0u, g, o);
    if (lane == 0) {
        float gold = g + start[tg[0]] + endsc[tg[len - 1]];
        d_loss[b] = logZ - gold;
    }
}

// ---------------- K6: mean reduce ----------------
__global__ void __launch_bounds__(64) k6_mean(float* out) {
    __shared__ float sh[64];
    int tid = threadIdx.x;
    sh[tid] = d_loss[tid];
    __syncthreads();
    for (int o = 32; o; o >>= 1) {
        if (tid < o) sh[tid] += sh[tid + o];
        __syncthreads();
    }
    if (tid == 0) out[0] = sh[0] * (1.f / BB);
}

// ---------------- launch ----------------
extern "C" void kernel_launch(void* const* d_in, const int* in_sizes, int n_in,
                              void* d_out, int out_size) {
    const int*   words   = (const int*)d_in[0];
    const int*   seq_len = (const int*)d_in[1];
    const int*   target  = (const int*)d_in[2];
    const float* embed   = (const float*)d_in[3];
    const float* gamma   = (const float*)d_in[4];
    const float* beta    = (const float*)d_in[5];
    const float* wihf    = (const float*)d_in[6];
    const float* whhf    = (const float*)d_in[7];
    const float* bf      = (const float*)d_in[8];
    const float* wihb    = (const float*)d_in[9];
    const float* whhb    = (const float*)d_in[10];
    const float* bb      = (const float*)d_in[11];
    const float* fcw     = (const float*)d_in[12];
    const float* fcb     = (const float*)d_in[13];
    const float* trans   = (const float*)d_in[14];
    const float* startsc = (const float*)d_in[15];
    const float* endsc   = (const float*)d_in[16];
    float* out = (float*)d_out;

    size_t hsmem = (size_t)HH * BB * sizeof(float);   // 51200 B dynamic
    cudaFuncSetAttribute(k3_lstm, cudaFuncAttributeMaxDynamicSharedMemorySize,
                         (int)hsmem);

    k0_init<<<1, 256>>>();
    k1_embed_ln<<<TT * BB / 8, 256>>>(words, embed, gamma, beta);
    {
        dim3 g(2 * G4 / 64, TT * BB / 128);
        k2_gemm<<<g, 256>>>(wihf, wihb, bf, bb);
    }
    k3_lstm<<<2 * NBD, 128, hsmem>>>(whhf, whhb, seq_len);
    k4_fc<<<TT * BB / 4, 128>>>(fcw, fcb);
    k5_crf<<<BB, 32>>>(seq_len, target, trans, startsc, endsc);
    k6_mean<<<1, 64>>>(out);
}

// round 4
// speedup vs baseline: 1.1157x; 1.1157x over previous
#include <cuda_runtime.h>
#include <math.h>

#define TT 512
#define BB 64
#define EE 256
#define HH 200
#define G4 800
#define CC 20
#define NBD 50   // blocks per direction in LSTM kernel
#define HSL 4    // h-units per block (HH / NBD)

typedef unsigned long long ull;
typedef unsigned int uint;

// ---------------- device scratch (no allocations allowed) ----------------
__device__ float d_x[TT * BB * EE];            // LN'd embeddings, [tok=t*64+b][e]
__device__ float d_G[2 * TT * G4 * BB];        // gates_x [dir][t][gate_row][b]
__device__ float d_hall[TT * BB * 2 * HH];     // h states [t][b][dir*H + j]
__device__ float d_hbuf[2 * 2 * HH * BB];      // h double buffer [dir][phase][j][b]
__device__ float d_logits[BB * TT * CC];       // log_softmax outputs [b][t][c]
__device__ float d_loss[BB];
__device__ unsigned d_bar[2];                  // per-direction phase-count barrier

// packed f32x2 FMA (SASS FFMA2 — only reachable via PTX)
__device__ __forceinline__ ull ffma2(ull a, ull b, ull c) {
    ull d;
    asm("fma.rn.f32x2 %0, %1, %2, %3;" : "=l"(d) : "l"(a), "l"(b), "l"(c));
    return d;
}
__device__ __forceinline__ float2 unpack2(ull v) {
    float2 r;
    asm("mov.b64 {%0, %1}, %2;" : "=f"(r.x), "=f"(r.y) : "l"(v));
    return r;
}
__device__ __forceinline__ uint f2tf32(float v) {
    uint r;
    asm("cvt.rna.tf32.f32 %0, %1;" : "=r"(r) : "f"(v));
    return r;
}

__device__ __forceinline__ float sigf(float x)  { return 1.f / (1.f + __expf(-x)); }
__device__ __forceinline__ float tanhfast(float x) { return 1.f - 2.f / (__expf(2.f * x) + 1.f); }

// ---------------- K0: init ----------------
__global__ void k0_init() {
    int tid = threadIdx.x;
    for (int i = tid; i < 2 * 2 * HH * BB; i += 256) d_hbuf[i] = 0.f;
    if (tid < 2) d_bar[tid] = 0u;
}

// ---------------- K1: embedding + LayerNorm (warp per token) ----------------
__global__ void __launch_bounds__(256) k1_embed_ln(
    const int* __restrict__ words, const float* __restrict__ embed,
    const float* __restrict__ gamma, const float* __restrict__ beta)
{
    int wid = threadIdx.x >> 5, lane = threadIdx.x & 31;
    int tok = blockIdx.x * 8 + wid;          // tok = t*64 + b
    int t = tok >> 6, b = tok & 63;
    int word = words[b * TT + t];
    const float4* src = (const float4*)(embed + (size_t)word * EE);
    float4 v0 = src[lane * 2], v1 = src[lane * 2 + 1];
    float s = v0.x + v0.y + v0.z + v0.w + v1.x + v1.y + v1.z + v1.w;
    float q = v0.x*v0.x + v0.y*v0.y + v0.z*v0.z + v0.w*v0.w
            + v1.x*v1.x + v1.y*v1.y + v1.z*v1.z + v1.w*v1.w;
    #pragma unroll
    for (int o = 16; o; o >>= 1) {
        s += __shfl_xor_sync(~0u, s, o);
        q += __shfl_xor_sync(~0u, q, o);
    }
    float mu  = s * (1.f / EE);
    float var = q * (1.f / EE) - mu * mu;
    float rs  = rsqrtf(var + 1e-5f);
    const float4* g4 = (const float4*)gamma;
    const float4* bt4 = (const float4*)beta;
    float4 ga = g4[lane*2], gb = g4[lane*2+1];
    float4 ba = bt4[lane*2], bb = bt4[lane*2+1];
    float4 o0, o1;
    o0.x = (v0.x-mu)*rs*ga.x + ba.x;  o0.y = (v0.y-mu)*rs*ga.y + ba.y;
    o0.z = (v0.z-mu)*rs*ga.z + ba.z;  o0.w = (v0.w-mu)*rs*ga.w + ba.w;
    o1.x = (v1.x-mu)*rs*gb.x + bb.x;  o1.y = (v1.y-mu)*rs*gb.y + bb.y;
    o1.z = (v1.z-mu)*rs*gb.z + bb.z;  o1.w = (v1.w-mu)*rs*gb.w + bb.w;
    float4* dst = (float4*)(d_x + (size_t)tok * EE);
    dst[lane*2] = o0; dst[lane*2+1] = o1;
}

// ---------------- K2: tf32 tensor-core GEMM  gates_x = X @ W_ih^T + b ----------------
// C[32768,1600]. BM=128, BN=64, BK=16, 256 threads = 8 warps (4m x 2n),
// warp tile 32x32 = 2 (m16) x 4 (n8) mma tiles, K via m16n8k8 tf32.
__global__ void __launch_bounds__(256) k2_gemm(
    const float* __restrict__ wihf, const float* __restrict__ wihb,
    const float* __restrict__ bf,   const float* __restrict__ bbias)
{
    __shared__ uint As[128 * 20];   // [m][k] stride 20 (tf32 bits)
    __shared__ uint Bs[64 * 20];    // [n][k] stride 20 (tf32 bits)

    int tid = threadIdx.x;
    int m0 = blockIdx.y * 128, n0 = blockIdx.x * 64;
    int wid = tid >> 5, lane = tid & 31;
    int wm = wid & 3, wn = wid >> 2;            // warp grid 4 x 2
    int gid = lane >> 2, ctid = lane & 3;

    float acc[2][4][4];
    #pragma unroll
    for (int mi = 0; mi < 2; ++mi)
        #pragma unroll
        for (int ni = 0; ni < 4; ++ni)
            #pragma unroll
            for (int r = 0; r < 4; ++r) acc[mi][ni][r] = 0.f;

    // load-index precompute
    int arow = tid >> 2;            // handled below per-i
    (void)arow;

    for (int k0 = 0; k0 < EE; k0 += 16) {
        // load A tile: 128x16 = 512 float4, 2 per thread
        #pragma unroll
        for (int i = 0; i < 2; ++i) {
            int j = tid + i * 256;
            int row = j >> 2, kq = (j & 3) * 4;
            float4 v = *(const float4*)(d_x + (size_t)(m0 + row) * EE + k0 + kq);
            uint* dst = As + row * 20 + kq;
            dst[0] = f2tf32(v.x); dst[1] = f2tf32(v.y);
            dst[2] = f2tf32(v.z); dst[3] = f2tf32(v.w);
        }
        // load B tile: 64x16 = 256 float4, 1 per thread
        {
            int row = tid >> 2, kq = (tid & 3) * 4;
            int nglob = n0 + row;
            const float* wrow = (nglob < G4) ? (wihf + (size_t)nglob * EE)
                                             : (wihb + (size_t)(nglob - G4) * EE);
            float4 v = *(const float4*)(wrow + k0 + kq);
            uint* dst = Bs + row * 20 + kq;
            dst[0] = f2tf32(v.x); dst[1] = f2tf32(v.y);
            dst[2] = f2tf32(v.z); dst[3] = f2tf32(v.w);
        }
        __syncthreads();

        #pragma unroll
        for (int k8 = 0; k8 < 16; k8 += 8) {
            uint afr[2][4], bfr[4][2];
            #pragma unroll
            for (int mi = 0; mi < 2; ++mi) {
                int mb = wm * 32 + mi * 16;
                const uint* ap = As + (mb + gid) * 20 + k8 + ctid;
                afr[mi][0] = ap[0];
                afr[mi][1] = ap[8 * 20];
                afr[mi][2] = ap[4];
                afr[mi][3] = ap[8 * 20 + 4];
            }
            #pragma unroll
            for (int ni = 0; ni < 4; ++ni) {
                int nb = wn * 32 + ni * 8;
                const uint* bp = Bs + (nb + gid) * 20 + k8 + ctid;
                bfr[ni][0] = bp[0];
                bfr[ni][1] = bp[4];
            }
            #pragma unroll
            for (int mi = 0; mi < 2; ++mi)
                #pragma unroll
                for (int ni = 0; ni < 4; ++ni) {
                    asm volatile(
                        "mma.sync.aligned.m16n8k8.row.col.f32.tf32.tf32.f32 "
                        "{%0,%1,%2,%3}, {%4,%5,%6,%7}, {%8,%9}, {%0,%1,%2,%3};"
                        : "+f"(acc[mi][ni][0]), "+f"(acc[mi][ni][1]),
                          "+f"(acc[mi][ni][2]), "+f"(acc[mi][ni][3])
                        : "r"(afr[mi][0]), "r"(afr[mi][1]),
                          "r"(afr[mi][2]), "r"(afr[mi][3]),
                          "r"(bfr[ni][0]), "r"(bfr[ni][1]));
                }
        }
        __syncthreads();
    }

    // epilogue: C[m][n] -> d_G[dir][t][r][b] + bias
    #pragma unroll
    for (int mi = 0; mi < 2; ++mi) {
        #pragma unroll
        for (int ni = 0; ni < 4; ++ni) {
            #pragma unroll
            for (int r = 0; r < 4; ++r) {
                int m = m0 + wm * 32 + mi * 16 + gid + (r >> 1) * 8;
                int n = n0 + wn * 32 + ni * 8 + 2 * ctid + (r & 1);
                int dir = (n >= G4) ? 1 : 0;
                int rr = n - dir * G4;
                float bias = dir ? bbias[rr] : bf[rr];
                int t = m >> 6, b = m & 63;
                d_G[(size_t)dir * (TT * G4 * BB) + ((size_t)t * G4 + rr) * BB + b]
                    = acc[mi][ni][r] + bias;
            }
        }
    }
}

// ---------------- K3: persistent bidirectional LSTM, fused activation ----------------
// 100 blocks (50/dir), 128 threads. warp <-> hidden unit, lane <-> batch pair.
// All four gates of one (unit, batch-pair) accumulate in one thread -> no staging.
__global__ void __launch_bounds__(128, 1) k3_lstm(
    const float* __restrict__ whhf, const float* __restrict__ whhb,
    const int* __restrict__ seq_len)
{
    extern __shared__ float dyn[];
    float* hsh = dyn;                             // [HH][BB] = 12800 floats
    float2* wsh2 = (float2*)(dyn + HH * BB);      // [k][unit][gate] dup pairs: 3200 float2

    int tid = threadIdx.x;
    int dir = blockIdx.x / NBD;
    int sl  = blockIdx.x % NBD;
    int j0  = sl * HSL;
    int w   = tid >> 5;           // local unit 0..3
    int l   = tid & 31;           // batch pair
    const float* whh = dir ? whhb : whhf;

    // W slice: wsh2[k*16 + u*4 + q] = dup(whh[(q*HH + j0 + u)*HH + k])
    for (int i = tid; i < HH * 16; i += 128) {
        int k = i >> 4, u = (i >> 2) & 3, q = i & 3;
        float v = whh[(size_t)(q * HH + j0 + u) * HH + k];
        wsh2[i] = make_float2(v, v);
    }

    int len0 = seq_len[2 * l], len1 = seq_len[2 * l + 1];
    float c0 = 0.f, c1 = 0.f;      // cell state in registers
    float hp0 = 0.f, hp1 = 0.f;    // held h for masked steps

    const float* G = d_G + (size_t)dir * (TT * G4 * BB);
    float* hb = d_hbuf + dir * (2 * HH * BB);
    const ulonglong2* w2 = (const ulonglong2*)wsh2;   // [k*8 + u*2 + {0,1}]

    // gate row base offsets for this thread (i,f,g,o)
    int rbase = j0 + w;
    size_t gi_off = ((size_t)(0 * HH + rbase)) * BB + 2 * l;
    size_t gf_off = ((size_t)(1 * HH + rbase)) * BB + 2 * l;
    size_t gg_off = ((size_t)(2 * HH + rbase)) * BB + 2 * l;
    size_t go_off = ((size_t)(3 * HH + rbase)) * BB + 2 * l;

    __syncthreads();

    // prefetch gx for first step
    int t0 = dir ? (TT - 1) : 0;
    ull pg_i = *(const ull*)(G + (size_t)t0 * G4 * BB + gi_off);
    ull pg_f = *(const ull*)(G + (size_t)t0 * G4 * BB + gf_off);
    ull pg_g = *(const ull*)(G + (size_t)t0 * G4 * BB + gg_off);
    ull pg_o = *(const ull*)(G + (size_t)t0 * G4 * BB + go_off);

    for (int st = 0; st < TT; ++st) {
        int t = dir ? (TT - 1 - st) : st;
        int p = st & 1;

        // h_prev (phase p) from L2 into shared
        {
            const float4* src = (const float4*)(hb + p * (HH * BB));
            float4* dst = (float4*)hsh;
            #pragma unroll 5
            for (int i = tid; i < HH * BB / 4; i += 128) dst[i] = __ldcg(src + i);
        }
        __syncthreads();

        ull ai = 0, af = 0, ag = 0, ao = 0;
        const float* hcol = hsh + 2 * l;
        #pragma unroll 4
        for (int k = 0; k < HH; ++k) {
            ull hv = *(const ull*)(hcol + k * BB);
            ulonglong2 wA = w2[k * 8 + w * 2];       // (wi,wi),(wf,wf)
            ulonglong2 wB = w2[k * 8 + w * 2 + 1];   // (wg,wg),(wo,wo)
            ai = ffma2(wA.x, hv, ai);
            af = ffma2(wA.y, hv, af);
            ag = ffma2(wB.x, hv, ag);
            ao = ffma2(wB.y, hv, ao);
        }

        float2 vi = unpack2(ai), vf = unpack2(af), vg = unpack2(ag), vo = unpack2(ao);
        float2 xi = unpack2(pg_i), xf = unpack2(pg_f), xg = unpack2(pg_g), xo = unpack2(pg_o);

        // batch 2l
        {
            float cn = sigf(vf.x + xf.x) * c0 + sigf(vi.x + xi.x) * tanhfast(vg.x + xg.x);
            float hn = sigf(vo.x + xo.x) * tanhfast(cn);
            bool valid = (t < len0);
            hp0 = valid ? hn : hp0;
            c0  = valid ? cn : c0;
        }
        // batch 2l+1
        {
            float cn = sigf(vf.y + xf.y) * c1 + sigf(vi.y + xi.y) * tanhfast(vg.y + xg.y);
            float hn = sigf(vo.y + xo.y) * tanhfast(cn);
            bool valid = (t < len1);
            hp1 = valid ? hn : hp1;
            c1  = valid ? cn : c1;
        }

        // stores: double buffer (for broadcast) + d_hall (for k4)
        __stcg((float2*)(hb + (p ^ 1) * (HH * BB) + (j0 + w) * BB + 2 * l),
               make_float2(hp0, hp1));
        d_hall[((size_t)t * BB + 2 * l) * (2 * HH) + dir * HH + j0 + w] = hp0;
        d_hall[((size_t)t * BB + 2 * l + 1) * (2 * HH) + dir * HH + j0 + w] = hp1;

        // prefetch next step's gx (h-independent) to hide DRAM latency behind barrier
        if (st + 1 < TT) {
            int tn = dir ? (TT - 2 - st) : (st + 1);
            const float* Gt = G + (size_t)tn * G4 * BB;
            pg_i = *(const ull*)(Gt + gi_off);
            pg_f = *(const ull*)(Gt + gf_off);
            pg_g = *(const ull*)(Gt + gg_off);
            pg_o = *(const ull*)(Gt + go_off);
        }

        // per-direction grid barrier (monotone phase counter; reset by K0)
        __threadfence();
        __syncthreads();
        if (tid == 0) {
            atomicAdd(&d_bar[dir], 1u);
            unsigned tgt = (unsigned)(st + 1) * NBD;
            while (*((volatile unsigned*)&d_bar[dir]) < tgt) { }
            __threadfence();
        }
        __syncthreads();
    }
}

// ---------------- K4: FC + log_softmax (warp per token) ----------------
__global__ void __launch_bounds__(128) k4_fc(
    const float* __restrict__ fcw, const float* __restrict__ fcb)
{
    __shared__ float wsh[CC * 401];   // pad 401 -> conflict-free column reads
    __shared__ float fbsh[CC];
    __shared__ float hs4[4][2 * HH];
    int tid = threadIdx.x;
    for (int i = tid; i < CC * 2 * HH; i += 128) {
        int c = i / (2 * HH), k = i % (2 * HH);
        wsh[c * 401 + k] = fcw[i];
    }
    if (tid < CC) fbsh[tid] = fcb[tid];
    __syncthreads();

    int w = tid >> 5, lane = tid & 31;
    int tok = blockIdx.x * 4 + w;                    // tok = t*64 + b
    for (int k = lane; k < 2 * HH; k += 32) hs4[w][k] = d_hall[(size_t)tok * (2 * HH) + k];
    __syncwarp();

    float acc = -1e30f;
    if (lane < CC) {
        acc = fbsh[lane];
        const float* wr = wsh + lane * 401;
        #pragma unroll 4
        for (int k = 0; k < 2 * HH; ++k) acc += hs4[w][k] * wr[k];
    }
    float m = acc;
    #pragma unroll
    for (int o = 16; o; o >>= 1) m = fmaxf(m, __shfl_xor_sync(~0u, m, o));
    float e = (lane < CC) ? __expf(acc - m) : 0.f;
    #pragma unroll
    for (int o = 16; o; o >>= 1) e += __shfl_xor_sync(~0u, e, o);
    float lse = m + __logf(e);
    if (lane < CC) {
        int t = tok >> 6, b = tok & 63;
        d_logits[((size_t)b * TT + t) * CC + lane] = acc - lse;
    }
}

// ---------------- K5: CRF NLL, one warp per batch element ----------------
__global__ void __launch_bounds__(32) k5_crf(
    const int* __restrict__ seq_len, const int* __restrict__ target,
    const float* __restrict__ trans, const float* __restrict__ start,
    const float* __restrict__ endsc)
{
    int b = blockIdx.x;
    int lane = threadIdx.x;
    int c = (lane < CC) ? lane : 0;
    int len = seq_len[b];
    const float* L = d_logits + (size_t)b * TT * CC;
    const int* tg = target + (size_t)b * TT;

    float tcol[CC];
    #pragma unroll
    for (int i = 0; i < CC; ++i) tcol[i] = (lane < CC) ? trans[i * CC + c] : 0.f;

    float alpha = (lane < CC) ? (start[c] + L[c]) : -1e30f;

    for (int t = 1; t < len; ++t) {
        float va[CC];
        #pragma unroll
        for (int i = 0; i < CC; ++i)
            va[i] = __shfl_sync(~0u, alpha, i) + tcol[i];
        float m = va[0];
        #pragma unroll
        for (int i = 1; i < CC; ++i) m = fmaxf(m, va[i]);
        float s = 0.f;
        #pragma unroll
        for (int i = 0; i < CC; ++i) s += __expf(va[i] - m);
        float emit = (lane < CC) ? L[t * CC + c] : 0.f;
        float nw = m + __logf(s) + emit;
        alpha = (lane < CC) ? nw : -1e30f;
    }

    // logZ = lse(alpha + end)
    float v = (lane < CC) ? (alpha + endsc[c]) : -1e30f;
    float m = v;
    #pragma unroll
    for (int o = 16; o; o >>= 1) m = fmaxf(m, __shfl_xor_sync(~0u, m, o));
    float s = __expf(v - m);
    if (lane >= CC) s = 0.f;
    #pragma unroll
    for (int o = 16; o; o >>= 1) s += __shfl_xor_sync(~0u, s, o);
    float logZ = m + __logf(s);

    // gold score
    float es = 0.f;
    for (int t = lane; t < len; t += 32) es += L[t * CC + tg[t]];
    float ts = 0.f;
    for (int t = lane; t < len - 1; t += 32) ts += trans[tg[t] * CC + tg[t + 1]];
    float g = es + ts;
    #pragma unroll
    for (int o = 16; o; o >>= 1) g += __shfl_xor_sync(~0u, g, o);
    if (lane == 0) {
        float gold = g + start[tg[0]] + endsc[tg[len - 1]];
        d_loss[b] = logZ - gold;
    }
}

// ---------------- K6: mean reduce ----------------
__global__ void __launch_bounds__(64) k6_mean(float* out) {
    __shared__ float sh[64];
    int tid = threadIdx.x;
    sh[tid] = d_loss[tid];
    __syncthreads();
    for (int o = 32; o; o >>= 1) {
        if (tid < o) sh[tid] += sh[tid + o];
        __syncthreads();
    }
    if (tid == 0) out[0] = sh[0] * (1.f / BB);
}

// ---------------- launch ----------------
extern "C" void kernel_launch(void* const* d_in, const int* in_sizes, int n_in,
                              void* d_out, int out_size) {
    const int*   words   = (const int*)d_in[0];
    const int*   seq_len = (const int*)d_in[1];
    const int*   target  = (const int*)d_in[2];
    const float* embed   = (const float*)d_in[3];
    const float* gamma   = (const float*)d_in[4];
    const float* beta    = (const float*)d_in[5];
    const float* wihf    = (const float*)d_in[6];
    const float* whhf    = (const float*)d_in[7];
    const float* bf      = (const float*)d_in[8];
    const float* wihb    = (const float*)d_in[9];
    const float* whhb    = (const float*)d_in[10];
    const float* bb      = (const float*)d_in[11];
    const float* fcw     = (const float*)d_in[12];
    const float* fcb     = (const float*)d_in[13];
    const float* trans   = (const float*)d_in[14];
    const float* startsc = (const float*)d_in[15];
    const float* endsc   = (const float*)d_in[16];
    float* out = (float*)d_out;

    // dynamic smem for k3: h broadcast (51200 B) + W slice dup (25600 B)
    size_t hsmem = (size_t)(HH * BB + 2 * HH * 16) * sizeof(float);   // 76800 B
    cudaFuncSetAttribute(k3_lstm, cudaFuncAttributeMaxDynamicSharedMemorySize,
                         (int)hsmem);

    k0_init<<<1, 256>>>();
    k1_embed_ln<<<TT * BB / 8, 256>>>(words, embed, gamma, beta);
    {
        dim3 g(2 * G4 / 64, TT * BB / 128);   // 25 x 256
        k2_gemm<<<g, 256>>>(wihf, wihb, bf, bb);
    }
    k3_lstm<<<2 * NBD, 128, hsmem>>>(whhf, whhb, seq_len);
    k4_fc<<<TT * BB / 4, 128>>>(fcw, fcb);
    k5_crf<<<BB, 32>>>(seq_len, target, trans, startsc, endsc);
    k6_mean<<<1, 64>>>(out);
}

// round 5
// speedup vs baseline: 1.3682x; 1.2263x over previous
#include <cuda_runtime.h>
#include <math.h>

#define TT 512
#define BB 64
#define EE 256
#define HH 200
#define G4 800
#define CC 20
#define NBD 50   // blocks per direction in LSTM kernel
#define HSL 4    // h-units per block (HH / NBD)
#define KT 25    // k-tiles of 8 in HH=200

typedef unsigned long long ull;
typedef unsigned int uint;

// ---------------- device scratch (no allocations allowed) ----------------
__device__ float d_x[TT * BB * EE];            // LN'd embeddings, [tok=t*64+b][e]
__device__ float d_G[2 * TT * G4 * BB];        // gates_x [dir][t][gate_row][b]
__device__ float d_hall[TT * BB * 2 * HH];     // h states [t][b][dir*H + j]
__device__ float d_hbuf[2 * 2 * HH * BB];      // h double buffer [dir][phase][j][b]
__device__ float d_logits[BB * TT * CC];       // log_softmax outputs [b][t][c]
__device__ float d_loss[BB];
__device__ unsigned d_flags[2][64];            // per-block progress flags

__device__ __forceinline__ uint f2tf32(float v) {
    uint r;
    asm("cvt.rna.tf32.f32 %0, %1;" : "=r"(r) : "f"(v));
    return r;
}
__device__ __forceinline__ float sigf(float x)  { return 1.f / (1.f + __expf(-x)); }
__device__ __forceinline__ float tanhfast(float x) { return 1.f - 2.f / (__expf(2.f * x) + 1.f); }

#define MMA_TF32(ACC, A, B0, B1)                                           \
    asm volatile(                                                          \
        "mma.sync.aligned.m16n8k8.row.col.f32.tf32.tf32.f32 "              \
        "{%0,%1,%2,%3}, {%4,%5,%6,%7}, {%8,%9}, {%0,%1,%2,%3};"            \
        : "+f"((ACC)[0]), "+f"((ACC)[1]), "+f"((ACC)[2]), "+f"((ACC)[3])   \
        : "r"((A)[0]), "r"((A)[1]), "r"((A)[2]), "r"((A)[3]),              \
          "r"(B0), "r"(B1))

// ---------------- K0: init ----------------
__global__ void k0_init() {
    int tid = threadIdx.x;
    for (int i = tid; i < 2 * 2 * HH * BB; i += 256) d_hbuf[i] = 0.f;
    if (tid < 128) ((unsigned*)d_flags)[tid] = 0u;
}

// ---------------- K1: embedding + LayerNorm (warp per token) ----------------
__global__ void __launch_bounds__(256) k1_embed_ln(
    const int* __restrict__ words, const float* __restrict__ embed,
    const float* __restrict__ gamma, const float* __restrict__ beta)
{
    int wid = threadIdx.x >> 5, lane = threadIdx.x & 31;
    int tok = blockIdx.x * 8 + wid;          // tok = t*64 + b
    int t = tok >> 6, b = tok & 63;
    int word = words[b * TT + t];
    const float4* src = (const float4*)(embed + (size_t)word * EE);
    float4 v0 = src[lane * 2], v1 = src[lane * 2 + 1];
    float s = v0.x + v0.y + v0.z + v0.w + v1.x + v1.y + v1.z + v1.w;
    float q = v0.x*v0.x + v0.y*v0.y + v0.z*v0.z + v0.w*v0.w
            + v1.x*v1.x + v1.y*v1.y + v1.z*v1.z + v1.w*v1.w;
    #pragma unroll
    for (int o = 16; o; o >>= 1) {
        s += __shfl_xor_sync(~0u, s, o);
        q += __shfl_xor_sync(~0u, q, o);
    }
    float mu  = s * (1.f / EE);
    float var = q * (1.f / EE) - mu * mu;
    float rs  = rsqrtf(var + 1e-5f);
    const float4* g4 = (const float4*)gamma;
    const float4* bt4 = (const float4*)beta;
    float4 ga = g4[lane*2], gb = g4[lane*2+1];
    float4 ba = bt4[lane*2], bb = bt4[lane*2+1];
    float4 o0, o1;
    o0.x = (v0.x-mu)*rs*ga.x + ba.x;  o0.y = (v0.y-mu)*rs*ga.y + ba.y;
    o0.z = (v0.z-mu)*rs*ga.z + ba.z;  o0.w = (v0.w-mu)*rs*ga.w + ba.w;
    o1.x = (v1.x-mu)*rs*gb.x + bb.x;  o1.y = (v1.y-mu)*rs*gb.y + bb.y;
    o1.z = (v1.z-mu)*rs*gb.z + bb.z;  o1.w = (v1.w-mu)*rs*gb.w + bb.w;
    float4* dst = (float4*)(d_x + (size_t)tok * EE);
    dst[lane*2] = o0; dst[lane*2+1] = o1;
}

// ---------------- K2: tf32 tensor-core GEMM  gates_x = X @ W_ih^T + b ----------------
__global__ void __launch_bounds__(256) k2_gemm(
    const float* __restrict__ wihf, const float* __restrict__ wihb,
    const float* __restrict__ bf,   const float* __restrict__ bbias)
{
    __shared__ uint As[128 * 20];   // [m][k] stride 20 (tf32 bits)
    __shared__ uint Bs[64 * 20];    // [n][k] stride 20 (tf32 bits)

    int tid = threadIdx.x;
    int m0 = blockIdx.y * 128, n0 = blockIdx.x * 64;
    int wid = tid >> 5, lane = tid & 31;
    int wm = wid & 3, wn = wid >> 2;            // warp grid 4 x 2
    int gid = lane >> 2, ctid = lane & 3;

    float acc[2][4][4];
    #pragma unroll
    for (int mi = 0; mi < 2; ++mi)
        #pragma unroll
        for (int ni = 0; ni < 4; ++ni)
            #pragma unroll
            for (int r = 0; r < 4; ++r) acc[mi][ni][r] = 0.f;

    for (int k0 = 0; k0 < EE; k0 += 16) {
        #pragma unroll
        for (int i = 0; i < 2; ++i) {
            int j = tid + i * 256;
            int row = j >> 2, kq = (j & 3) * 4;
            float4 v = *(const float4*)(d_x + (size_t)(m0 + row) * EE + k0 + kq);
            uint* dst = As + row * 20 + kq;
            dst[0] = f2tf32(v.x); dst[1] = f2tf32(v.y);
            dst[2] = f2tf32(v.z); dst[3] = f2tf32(v.w);
        }
        {
            int row = tid >> 2, kq = (tid & 3) * 4;
            int nglob = n0 + row;
            const float* wrow = (nglob < G4) ? (wihf + (size_t)nglob * EE)
                                             : (wihb + (size_t)(nglob - G4) * EE);
            float4 v = *(const float4*)(wrow + k0 + kq);
            uint* dst = Bs + row * 20 + kq;
            dst[0] = f2tf32(v.x); dst[1] = f2tf32(v.y);
            dst[2] = f2tf32(v.z); dst[3] = f2tf32(v.w);
        }
        __syncthreads();

        #pragma unroll
        for (int k8 = 0; k8 < 16; k8 += 8) {
            uint afr[2][4], bfr[4][2];
            #pragma unroll
            for (int mi = 0; mi < 2; ++mi) {
                int mb = wm * 32 + mi * 16;
                const uint* ap = As + (mb + gid) * 20 + k8 + ctid;
                afr[mi][0] = ap[0];
                afr[mi][1] = ap[8 * 20];
                afr[mi][2] = ap[4];
                afr[mi][3] = ap[8 * 20 + 4];
            }
            #pragma unroll
            for (int ni = 0; ni < 4; ++ni) {
                int nb = wn * 32 + ni * 8;
                const uint* bp = Bs + (nb + gid) * 20 + k8 + ctid;
                bfr[ni][0] = bp[0];
                bfr[ni][1] = bp[4];
            }
            #pragma unroll
            for (int mi = 0; mi < 2; ++mi)
                #pragma unroll
                for (int ni = 0; ni < 4; ++ni)
                    MMA_TF32(acc[mi][ni], afr[mi], bfr[ni][0], bfr[ni][1]);
        }
        __syncthreads();
    }

    #pragma unroll
    for (int mi = 0; mi < 2; ++mi)
        #pragma unroll
        for (int ni = 0; ni < 4; ++ni)
            #pragma unroll
            for (int r = 0; r < 4; ++r) {
                int m = m0 + wm * 32 + mi * 16 + gid + (r >> 1) * 8;
                int n = n0 + wn * 32 + ni * 8 + 2 * ctid + (r & 1);
                int dir = (n >= G4) ? 1 : 0;
                int rr = n - dir * G4;
                float bias = dir ? bbias[rr] : bf[rr];
                int t = m >> 6, b = m & 63;
                d_G[(size_t)dir * (TT * G4 * BB) + ((size_t)t * G4 + rr) * BB + b]
                    = acc[mi][ni][r] + bias;
            }
}

// ---------------- K3: persistent BiLSTM, tensor-core recurrence ----------------
// 100 blocks (50/dir), 128 threads. Per block/step: W(16x200) @ h(200x64) via
// m16n8k8 tf32 with W resident in registers. Flag-array barrier, no atomics.
__global__ void __launch_bounds__(128, 1) k3_lstm(
    const float* __restrict__ whhf, const float* __restrict__ whhb,
    const int* __restrict__ seq_len)
{
    extern __shared__ float hsh[];   // [HH][72] padded h tile, 57600 B

    int tid = threadIdx.x;
    int dir = blockIdx.x / NBD;
    int sl  = blockIdx.x % NBD;
    int j0  = sl * HSL;
    const float* whh = dir ? whhb : whhf;

    int wid = tid >> 5, lane = tid & 31;
    int gid = lane >> 2, ctid = lane & 3;
    int u   = gid & 3;            // local hidden unit 0..3
    int q1  = gid >> 2;           // 0: rows {i,g}; 1: rows {f,o}
    int bnw = wid * 16;           // warp batch base
    int b0  = bnw + q1 * 8 + 2 * ctid;   // this thread's batch pair (b0, b0+1)

    // persistent A fragments: W rows r16 = q*4+u, cols k (tf32)
    uint aw[KT][4];
    {
        int rowA = q1 * HH + j0 + u;         // mma row gid   -> gate q1
        int rowB = (q1 + 2) * HH + j0 + u;   // mma row gid+8 -> gate q1+2
        #pragma unroll
        for (int kt = 0; kt < KT; ++kt) {
            int k0 = kt * 8;
            aw[kt][0] = f2tf32(whh[(size_t)rowA * HH + k0 + ctid]);
            aw[kt][1] = f2tf32(whh[(size_t)rowB * HH + k0 + ctid]);
            aw[kt][2] = f2tf32(whh[(size_t)rowA * HH + k0 + ctid + 4]);
            aw[kt][3] = f2tf32(whh[(size_t)rowB * HH + k0 + ctid + 4]);
        }
    }

    int len0 = seq_len[b0], len1 = seq_len[b0 + 1];
    float c0 = 0.f, c1 = 0.f, hp0 = 0.f, hp1 = 0.f;

    const float* G = d_G + (size_t)dir * (TT * G4 * BB);
    float* hb = d_hbuf + dir * (2 * HH * BB);
    unsigned* flags = &d_flags[dir][0];

    // gx offsets (gates i,f,g,o) for this thread's unit/batch-pair
    size_t goff[4];
    #pragma unroll
    for (int q = 0; q < 4; ++q)
        goff[q] = ((size_t)(q * HH + j0 + u)) * BB + b0;

    for (int st = 0; st < TT; ++st) {
        int t = dir ? (TT - 1 - st) : st;
        int p = st & 1;
        const float* Gt = G + (size_t)t * G4 * BB;

        // prefetch gx (h-independent) to overlap the flag wait
        float2 xg[4];
        #pragma unroll
        for (int q = 0; q < 4; ++q) xg[q] = *(const float2*)(Gt + goff[q]);

        // flag barrier: all blocks must have completed step st-1
        if (tid < NBD) {
            unsigned v;
            do {
                asm volatile("ld.acquire.gpu.u32 %0, [%1];"
                             : "=r"(v) : "l"(flags + tid));
            } while (v < (unsigned)st);
        }
        __syncthreads();

        // h_prev (phase p) L2 -> padded smem tile [k][72]
        {
            const float4* src = (const float4*)(hb + p * (HH * BB));
            #pragma unroll
            for (int i = tid; i < HH * BB / 4; i += 128) {
                float4 v = __ldcg(src + i);
                int k = i >> 4, b = (i & 15) * 4;
                *(float4*)&hsh[k * 72 + b] = v;
            }
        }
        __syncthreads();

        // gates(16 x 64) = W @ h  via 2 n-tiles x 25 k-tiles of m16n8k8
        float acc0[4] = {0.f, 0.f, 0.f, 0.f};
        float acc1[4] = {0.f, 0.f, 0.f, 0.f};
        #pragma unroll
        for (int kt = 0; kt < KT; ++kt) {
            const float* hk = hsh + (kt * 8 + ctid) * 72;
            uint b00 = __float_as_uint(hk[bnw + gid]);
            uint b01 = __float_as_uint(hk[4 * 72 + bnw + gid]);
            uint b10 = __float_as_uint(hk[bnw + 8 + gid]);
            uint b11 = __float_as_uint(hk[4 * 72 + bnw + 8 + gid]);
            MMA_TF32(acc0, aw[kt], b00, b01);
            MMA_TF32(acc1, aw[kt], b10, b11);
        }

        // exchange gate pairs with partner (lane ^ 16): each thread keeps
        // its own n-tile (q1) and receives the other two gates for it.
        float s0 = q1 ? acc0[0] : acc1[0];
        float s1 = q1 ? acc0[1] : acc1[1];
        float s2 = q1 ? acc0[2] : acc1[2];
        float s3 = q1 ? acc0[3] : acc1[3];
        float o0 = __shfl_xor_sync(~0u, s0, 16);
        float o1 = __shfl_xor_sync(~0u, s1, 16);
        float o2 = __shfl_xor_sync(~0u, s2, 16);
        float o3 = __shfl_xor_sync(~0u, s3, 16);
        float m0 = q1 ? acc1[0] : acc0[0];
        float m1 = q1 ? acc1[1] : acc0[1];
        float m2 = q1 ? acc1[2] : acc0[2];
        float m3 = q1 ? acc1[3] : acc0[3];
        // gate i,f,g,o for batch b0 (col 2ctid) and b0+1 (col 2ctid+1)
        float gi0 = q1 ? o0 : m0,  gf0 = q1 ? m0 : o0;
        float gg0 = q1 ? o2 : m2,  go0 = q1 ? m2 : o2;
        float gi1 = q1 ? o1 : m1,  gf1 = q1 ? m1 : o1;
        float gg1 = q1 ? o3 : m3,  go1 = q1 ? m3 : o3;

        // activations + packed-sequence masking
        {
            float cn = sigf(gf0 + xg[1].x) * c0
                     + sigf(gi0 + xg[0].x) * tanhfast(gg0 + xg[2].x);
            float hn = sigf(go0 + xg[3].x) * tanhfast(cn);
            bool valid = (t < len0);
            hp0 = valid ? hn : hp0;
            c0  = valid ? cn : c0;
        }
        {
            float cn = sigf(gf1 + xg[1].y) * c1
                     + sigf(gi1 + xg[0].y) * tanhfast(gg1 + xg[2].y);
            float hn = sigf(go1 + xg[3].y) * tanhfast(cn);
            bool valid = (t < len1);
            hp1 = valid ? hn : hp1;
            c1  = valid ? cn : c1;
        }

        // broadcast h (tf32-rounded so consumers' B-operands need no cvt)
        float h0s = __uint_as_float(f2tf32(hp0));
        float h1s = __uint_as_float(f2tf32(hp1));
        __stcg((float2*)(hb + (p ^ 1) * (HH * BB) + (j0 + u) * BB + b0),
               make_float2(h0s, h1s));
        d_hall[((size_t)t * BB + b0) * (2 * HH) + dir * HH + j0 + u] = hp0;
        d_hall[((size_t)t * BB + b0 + 1) * (2 * HH) + dir * HH + j0 + u] = hp1;

        __threadfence();
        __syncthreads();
        if (tid == 0)
            asm volatile("st.release.gpu.u32 [%0], %1;"
                         :: "l"(flags + sl), "r"((unsigned)(st + 1)));
    }
}

// ---------------- K4: FC + log_softmax (warp per token) ----------------
__global__ void __launch_bounds__(128) k4_fc(
    const float* __restrict__ fcw, const float* __restrict__ fcb)
{
    __shared__ float wsh[CC * 401];
    __shared__ float fbsh[CC];
    __shared__ float hs4[4][2 * HH];
    int tid = threadIdx.x;
    for (int i = tid; i < CC * 2 * HH; i += 128) {
        int c = i / (2 * HH), k = i % (2 * HH);
        wsh[c * 401 + k] = fcw[i];
    }
    if (tid < CC) fbsh[tid] = fcb[tid];
    __syncthreads();

    int w = tid >> 5, lane = tid & 31;
    int tok = blockIdx.x * 4 + w;                    // tok = t*64 + b
    for (int k = lane; k < 2 * HH; k += 32) hs4[w][k] = d_hall[(size_t)tok * (2 * HH) + k];
    __syncwarp();

    float acc = -1e30f;
    if (lane < CC) {
        acc = fbsh[lane];
        const float* wr = wsh + lane * 401;
        #pragma unroll 4
        for (int k = 0; k < 2 * HH; ++k) acc += hs4[w][k] * wr[k];
    }
    float m = acc;
    #pragma unroll
    for (int o = 16; o; o >>= 1) m = fmaxf(m, __shfl_xor_sync(~0u, m, o));
    float e = (lane < CC) ? __expf(acc - m) : 0.f;
    #pragma unroll
    for (int o = 16; o; o >>= 1) e += __shfl_xor_sync(~0u, e, o);
    float lse = m + __logf(e);
    if (lane < CC) {
        int t = tok >> 6, b = tok & 63;
        d_logits[((size_t)b * TT + t) * CC + lane] = acc - lse;
    }
}

// ---------------- K5: CRF NLL, one warp per batch element ----------------
__global__ void __launch_bounds__(32) k5_crf(
    const int* __restrict__ seq_len, const int* __restrict__ target,
    const float* __restrict__ trans, const float* __restrict__ start,
    const float* __restrict__ endsc)
{
    int b = blockIdx.x;
    int lane = threadIdx.x;
    int c = (lane < CC) ? lane : 0;
    int len = seq_len[b];
    const float* L = d_logits + (size_t)b * TT * CC;
    const int* tg = target + (size_t)b * TT;

    float tcol[CC];
    #pragma unroll
    for (int i = 0; i < CC; ++i) tcol[i] = (lane < CC) ? trans[i * CC + c] : 0.f;

    float alpha = (lane < CC) ? (start[c] + L[c]) : -1e30f;

    for (int t = 1; t < len; ++t) {
        float va[CC];
        #pragma unroll
        for (int i = 0; i < CC; ++i)
            va[i] = __shfl_sync(~0u, alpha, i) + tcol[i];
        float m = va[0];
        #pragma unroll
        for (int i = 1; i < CC; ++i) m = fmaxf(m, va[i]);
        float s = 0.f;
        #pragma unroll
        for (int i = 0; i < CC; ++i) s += __expf(va[i] - m);
        float emit = (lane < CC) ? L[t * CC + c] : 0.f;
        float nw = m + __logf(s) + emit;
        alpha = (lane < CC) ? nw : -1e30f;
    }

    float v = (lane < CC) ? (alpha + endsc[c]) : -1e30f;
    float m = v;
    #pragma unroll
    for (int o = 16; o; o >>= 1) m = fmaxf(m, __shfl_xor_sync(~0u, m, o));
    float s = __expf(v - m);
    if (lane >= CC) s = 0.f;
    #pragma unroll
    for (int o = 16; o; o >>= 1) s += __shfl_xor_sync(~0u, s, o);
    float logZ = m + __logf(s);

    float es = 0.f;
    for (int t = lane; t < len; t += 32) es += L[t * CC + tg[t]];
    float ts = 0.f;
    for (int t = lane; t < len - 1; t += 32) ts += trans[tg[t] * CC + tg[t + 1]];
    float g = es + ts;
    #pragma unroll
    for (int o = 16; o; o >>= 1) g += __shfl_xor_sync(~0u, g, o);
    if (lane == 0) {
        float gold = g + start[tg[0]] + endsc[tg[len - 1]];
        d_loss[b] = logZ - gold;
    }
}

// ---------------- K6: mean reduce ----------------
__global__ void __launch_bounds__(64) k6_mean(float* out) {
    __shared__ float sh[64];
    int tid = threadIdx.x;
    sh[tid] = d_loss[tid];
    __syncthreads();
    for (int o = 32; o; o >>= 1) {
        if (tid < o) sh[tid] += sh[tid + o];
        __syncthreads();
    }
    if (tid == 0) out[0] = sh[0] * (1.f / BB);
}

// ---------------- launch ----------------
extern "C" void kernel_launch(void* const* d_in, const int* in_sizes, int n_in,
                              void* d_out, int out_size) {
    const int*   words   = (const int*)d_in[0];
    const int*   seq_len = (const int*)d_in[1];
    const int*   target  = (const int*)d_in[2];
    const float* embed   = (const float*)d_in[3];
    const float* gamma   = (const float*)d_in[4];
    const float* beta    = (const float*)d_in[5];
    const float* wihf    = (const float*)d_in[6];
    const float* whhf    = (const float*)d_in[7];
    const float* bf      = (const float*)d_in[8];
    const float* wihb    = (const float*)d_in[9];
    const float* whhb    = (const float*)d_in[10];
    const float* bb      = (const float*)d_in[11];
    const float* fcw     = (const float*)d_in[12];
    const float* fcb     = (const float*)d_in[13];
    const float* trans   = (const float*)d_in[14];
    const float* startsc = (const float*)d_in[15];
    const float* endsc   = (const float*)d_in[16];
    float* out = (float*)d_out;

    size_t hsmem = (size_t)HH * 72 * sizeof(float);   // 57600 B
    cudaFuncSetAttribute(k3_lstm, cudaFuncAttributeMaxDynamicSharedMemorySize,
                         (int)hsmem);

    k0_init<<<1, 256>>>();
    k1_embed_ln<<<TT * BB / 8, 256>>>(words, embed, gamma, beta);
    {
        dim3 g(2 * G4 / 64, TT * BB / 128);   // 25 x 256
        k2_gemm<<<g, 256>>>(wihf, wihb, bf, bb);
    }
    k3_lstm<<<2 * NBD, 128, hsmem>>>(whhf, whhb, seq_len);
    k4_fc<<<TT * BB / 4, 128>>>(fcw, fcb);
    k5_crf<<<BB, 32>>>(seq_len, target, trans, startsc, endsc);
    k6_mean<<<1, 64>>>(out);
}

// round 6
// speedup vs baseline: 1.4101x; 1.0306x over previous
#include <cuda_runtime.h>
#include <math.h>

#define TT 512
#define BB 64
#define EE 256
#define HH 200
#define G4 800
#define CC 20
#define NBD 50   // blocks per direction in LSTM kernel
#define HSL 4    // h-units per block (HH / NBD)
#define KT 25    // k-tiles of 8 in HH=200

typedef unsigned long long ull;
typedef unsigned int uint;

// ---------------- device scratch (no allocations allowed) ----------------
__device__ float d_x[TT * BB * EE];            // LN'd embeddings, [tok=t*64+b][e]
__device__ float d_G[2 * TT * G4 * BB];        // gates_x [dir][t][gate_row][b]
__device__ float d_hall[TT * BB * 2 * HH];     // h states [t][b][dir*H + j]
__device__ float d_hbuf[2 * 2 * NBD * 256];    // h dbuf [dir][phase][slice][u*64+b]
__device__ float d_logits[BB * TT * CC];       // log_softmax outputs [b][t][c]
__device__ float d_loss[BB];
__device__ unsigned d_flagsp[2][NBD][32];      // flags spread 128B apart

__device__ __forceinline__ uint f2tf32(float v) {
    uint r;
    asm("cvt.rna.tf32.f32 %0, %1;" : "=r"(r) : "f"(v));
    return r;
}
__device__ __forceinline__ float sigf(float x)  { return 1.f / (1.f + __expf(-x)); }
__device__ __forceinline__ float tanhfast(float x) { return 1.f - 2.f / (__expf(2.f * x) + 1.f); }

#define MMA_TF32(ACC, A, B0, B1)                                           \
    asm volatile(                                                          \
        "mma.sync.aligned.m16n8k8.row.col.f32.tf32.tf32.f32 "              \
        "{%0,%1,%2,%3}, {%4,%5,%6,%7}, {%8,%9}, {%0,%1,%2,%3};"            \
        : "+f"((ACC)[0]), "+f"((ACC)[1]), "+f"((ACC)[2]), "+f"((ACC)[3])   \
        : "r"((A)[0]), "r"((A)[1]), "r"((A)[2]), "r"((A)[3]),              \
          "r"(B0), "r"(B1))

// ---------------- K0: init ----------------
__global__ void k0_init() {
    int tid = threadIdx.x;
    for (int i = tid; i < 2 * 2 * NBD * 256; i += 256) d_hbuf[i] = 0.f;
    for (int i = tid; i < 2 * NBD * 32; i += 256) ((unsigned*)d_flagsp)[i] = 0u;
}

// ---------------- K1: embedding + LayerNorm (warp per token) ----------------
__global__ void __launch_bounds__(256) k1_embed_ln(
    const int* __restrict__ words, const float* __restrict__ embed,
    const float* __restrict__ gamma, const float* __restrict__ beta)
{
    int wid = threadIdx.x >> 5, lane = threadIdx.x & 31;
    int tok = blockIdx.x * 8 + wid;          // tok = t*64 + b
    int t = tok >> 6, b = tok & 63;
    int word = words[b * TT + t];
    const float4* src = (const float4*)(embed + (size_t)word * EE);
    float4 v0 = src[lane * 2], v1 = src[lane * 2 + 1];
    float s = v0.x + v0.y + v0.z + v0.w + v1.x + v1.y + v1.z + v1.w;
    float q = v0.x*v0.x + v0.y*v0.y + v0.z*v0.z + v0.w*v0.w
            + v1.x*v1.x + v1.y*v1.y + v1.z*v1.z + v1.w*v1.w;
    #pragma unroll
    for (int o = 16; o; o >>= 1) {
        s += __shfl_xor_sync(~0u, s, o);
        q += __shfl_xor_sync(~0u, q, o);
    }
    float mu  = s * (1.f / EE);
    float var = q * (1.f / EE) - mu * mu;
    float rs  = rsqrtf(var + 1e-5f);
    const float4* g4 = (const float4*)gamma;
    const float4* bt4 = (const float4*)beta;
    float4 ga = g4[lane*2], gb = g4[lane*2+1];
    float4 ba = bt4[lane*2], bb = bt4[lane*2+1];
    float4 o0, o1;
    o0.x = (v0.x-mu)*rs*ga.x + ba.x;  o0.y = (v0.y-mu)*rs*ga.y + ba.y;
    o0.z = (v0.z-mu)*rs*ga.z + ba.z;  o0.w = (v0.w-mu)*rs*ga.w + ba.w;
    o1.x = (v1.x-mu)*rs*gb.x + bb.x;  o1.y = (v1.y-mu)*rs*gb.y + bb.y;
    o1.z = (v1.z-mu)*rs*gb.z + bb.z;  o1.w = (v1.w-mu)*rs*gb.w + bb.w;
    float4* dst = (float4*)(d_x + (size_t)tok * EE);
    dst[lane*2] = o0; dst[lane*2+1] = o1;
}

// ---------------- K2: tf32 tensor-core GEMM  gates_x = X @ W_ih^T + b ----------------
__global__ void __launch_bounds__(256) k2_gemm(
    const float* __restrict__ wihf, const float* __restrict__ wihb,
    const float* __restrict__ bf,   const float* __restrict__ bbias)
{
    __shared__ uint As[128 * 20];   // [m][k] stride 20 (tf32 bits)
    __shared__ uint Bs[64 * 20];    // [n][k] stride 20 (tf32 bits)

    int tid = threadIdx.x;
    int m0 = blockIdx.y * 128, n0 = blockIdx.x * 64;
    int wid = tid >> 5, lane = tid & 31;
    int wm = wid & 3, wn = wid >> 2;            // warp grid 4 x 2
    int gid = lane >> 2, ctid = lane & 3;

    float acc[2][4][4];
    #pragma unroll
    for (int mi = 0; mi < 2; ++mi)
        #pragma unroll
        for (int ni = 0; ni < 4; ++ni)
            #pragma unroll
            for (int r = 0; r < 4; ++r) acc[mi][ni][r] = 0.f;

    for (int k0 = 0; k0 < EE; k0 += 16) {
        #pragma unroll
        for (int i = 0; i < 2; ++i) {
            int j = tid + i * 256;
            int row = j >> 2, kq = (j & 3) * 4;
            float4 v = *(const float4*)(d_x + (size_t)(m0 + row) * EE + k0 + kq);
            uint* dst = As + row * 20 + kq;
            dst[0] = f2tf32(v.x); dst[1] = f2tf32(v.y);
            dst[2] = f2tf32(v.z); dst[3] = f2tf32(v.w);
        }
        {
            int row = tid >> 2, kq = (tid & 3) * 4;
            int nglob = n0 + row;
            const float* wrow = (nglob < G4) ? (wihf + (size_t)nglob * EE)
                                             : (wihb + (size_t)(nglob - G4) * EE);
            float4 v = *(const float4*)(wrow + k0 + kq);
            uint* dst = Bs + row * 20 + kq;
            dst[0] = f2tf32(v.x); dst[1] = f2tf32(v.y);
            dst[2] = f2tf32(v.z); dst[3] = f2tf32(v.w);
        }
        __syncthreads();

        #pragma unroll
        for (int k8 = 0; k8 < 16; k8 += 8) {
            uint afr[2][4], bfr[4][2];
            #pragma unroll
            for (int mi = 0; mi < 2; ++mi) {
                int mb = wm * 32 + mi * 16;
                const uint* ap = As + (mb + gid) * 20 + k8 + ctid;
                afr[mi][0] = ap[0];
                afr[mi][1] = ap[8 * 20];
                afr[mi][2] = ap[4];
                afr[mi][3] = ap[8 * 20 + 4];
            }
            #pragma unroll
            for (int ni = 0; ni < 4; ++ni) {
                int nb = wn * 32 + ni * 8;
                const uint* bp = Bs + (nb + gid) * 20 + k8 + ctid;
                bfr[ni][0] = bp[0];
                bfr[ni][1] = bp[4];
            }
            #pragma unroll
            for (int mi = 0; mi < 2; ++mi)
                #pragma unroll
                for (int ni = 0; ni < 4; ++ni)
                    MMA_TF32(acc[mi][ni], afr[mi], bfr[ni][0], bfr[ni][1]);
        }
        __syncthreads();
    }

    #pragma unroll
    for (int mi = 0; mi < 2; ++mi)
        #pragma unroll
        for (int ni = 0; ni < 4; ++ni)
            #pragma unroll
            for (int r = 0; r < 4; ++r) {
                int m = m0 + wm * 32 + mi * 16 + gid + (r >> 1) * 8;
                int n = n0 + wn * 32 + ni * 8 + 2 * ctid + (r & 1);
                int dir = (n >= G4) ? 1 : 0;
                int rr = n - dir * G4;
                float bias = dir ? bbias[rr] : bf[rr];
                int t = m >> 6, b = m & 63;
                d_G[(size_t)dir * (TT * G4 * BB) + ((size_t)t * G4 + rr) * BB + b]
                    = acc[mi][ni][r] + bias;
            }
}

// ---------------- K3: persistent BiLSTM, tensor-core recurrence ----------------
// 100 blocks (50/dir), 128 threads. Per-producer flags (128B apart), eager
// slice loading overlapped with skew, own slice scattered from registers.
__global__ void __launch_bounds__(128, 1) k3_lstm(
    const float* __restrict__ whhf, const float* __restrict__ whhb,
    const int* __restrict__ seq_len)
{
    extern __shared__ float hsh[];   // [HH][72] padded h tile, 57600 B

    int tid = threadIdx.x;
    int dir = blockIdx.x / NBD;
    int sl  = blockIdx.x % NBD;
    int j0  = sl * HSL;
    const float* whh = dir ? whhb : whhf;

    int wid = tid >> 5, lane = tid & 31;
    int gid = lane >> 2, ctid = lane & 3;
    int u   = gid & 3;            // local hidden unit 0..3
    int q1  = gid >> 2;           // 0: rows {i,g}; 1: rows {f,o}
    int bnw = wid * 16;           // warp batch base
    int b0  = bnw + q1 * 8 + 2 * ctid;   // this thread's batch pair (b0, b0+1)

    // persistent A fragments: W rows r16 = q*4+u, cols k (tf32)
    uint aw[KT][4];
    {
        int rowA = q1 * HH + j0 + u;         // mma row gid   -> gate q1
        int rowB = (q1 + 2) * HH + j0 + u;   // mma row gid+8 -> gate q1+2
        #pragma unroll
        for (int kt = 0; kt < KT; ++kt) {
            int k0 = kt * 8;
            aw[kt][0] = f2tf32(whh[(size_t)rowA * HH + k0 + ctid]);
            aw[kt][1] = f2tf32(whh[(size_t)rowB * HH + k0 + ctid]);
            aw[kt][2] = f2tf32(whh[(size_t)rowA * HH + k0 + ctid + 4]);
            aw[kt][3] = f2tf32(whh[(size_t)rowB * HH + k0 + ctid + 4]);
        }
    }

    int len0 = seq_len[b0], len1 = seq_len[b0 + 1];
    float c0 = 0.f, c1 = 0.f, hp0 = 0.f, hp1 = 0.f;
    float h0s = 0.f, h1s = 0.f;   // tf32-rounded h (what consumers see)

    const float* G = d_G + (size_t)dir * (TT * G4 * BB);
    float* hb = d_hbuf + dir * (2 * NBD * 256);
    unsigned* flg = &d_flagsp[dir][0][0];   // stride 32 u32 per producer

    // eager loader assignment: 2 threads per foreign slice
    int ls2 = tid >> 1, lhalf = tid & 1;
    int lslice = ls2 + (ls2 >= sl ? 1 : 0);
    bool loader = (tid < 2 * (NBD - 1));

    // gx offsets (gates i,f,g,o) for this thread's unit/batch-pair
    size_t goff[4];
    #pragma unroll
    for (int q = 0; q < 4; ++q)
        goff[q] = ((size_t)(q * HH + j0 + u)) * BB + b0;

    for (int st = 0; st < TT; ++st) {
        int t = dir ? (TT - 1 - st) : st;
        int p = st & 1;
        const float* Gt = G + (size_t)t * G4 * BB;

        // prefetch gx (h-independent) to overlap the flag wait
        float2 xg[4];
        #pragma unroll
        for (int q = 0; q < 4; ++q) xg[q] = *(const float2*)(Gt + goff[q]);

        // own slice: scatter rounded h directly from registers (no L2 trip)
        *(float2*)&hsh[(j0 + u) * 72 + b0] = make_float2(h0s, h1s);

        // foreign slices: poll producer flag, then load+scatter its 1KB slice
        if (loader) {
            unsigned v;
            const unsigned* fp = flg + lslice * 32;
            do {
                asm volatile("ld.acquire.gpu.u32 %0, [%1];" : "=r"(v) : "l"(fp));
            } while (v < (unsigned)st);
            const float4* src = (const float4*)(hb + p * (NBD * 256) + lslice * 256)
                                + lhalf * 32;
            #pragma unroll 8
            for (int j = 0; j < 32; ++j) {
                float4 hv = __ldcg(src + j);
                int idx = lhalf * 32 + j;           // float4 index in slice
                int uu = idx >> 4, b4 = (idx & 15) * 4;
                *(float4*)&hsh[(4 * lslice + uu) * 72 + b4] = hv;
            }
        }
        __syncthreads();

        // gates(16 x 64) = W @ h  via 2 n-tiles x 25 k-tiles of m16n8k8
        float acc0[4] = {0.f, 0.f, 0.f, 0.f};
        float acc1[4] = {0.f, 0.f, 0.f, 0.f};
        #pragma unroll
        for (int kt = 0; kt < KT; ++kt) {
            const float* hk = hsh + (kt * 8 + ctid) * 72;
            uint b00 = __float_as_uint(hk[bnw + gid]);
            uint b01 = __float_as_uint(hk[4 * 72 + bnw + gid]);
            uint b10 = __float_as_uint(hk[bnw + 8 + gid]);
            uint b11 = __float_as_uint(hk[4 * 72 + bnw + 8 + gid]);
            MMA_TF32(acc0, aw[kt], b00, b01);
            MMA_TF32(acc1, aw[kt], b10, b11);
        }

        // exchange gate pairs with partner (lane ^ 16)
        float s0 = q1 ? acc0[0] : acc1[0];
        float s1 = q1 ? acc0[1] : acc1[1];
        float s2 = q1 ? acc0[2] : acc1[2];
        float s3 = q1 ? acc0[3] : acc1[3];
        float o0 = __shfl_xor_sync(~0u, s0, 16);
        float o1 = __shfl_xor_sync(~0u, s1, 16);
        float o2 = __shfl_xor_sync(~0u, s2, 16);
        float o3 = __shfl_xor_sync(~0u, s3, 16);
        float m0 = q1 ? acc1[0] : acc0[0];
        float m1 = q1 ? acc1[1] : acc0[1];
        float m2 = q1 ? acc1[2] : acc0[2];
        float m3 = q1 ? acc1[3] : acc0[3];
        float gi0 = q1 ? o0 : m0,  gf0 = q1 ? m0 : o0;
        float gg0 = q1 ? o2 : m2,  go0 = q1 ? m2 : o2;
        float gi1 = q1 ? o1 : m1,  gf1 = q1 ? m1 : o1;
        float gg1 = q1 ? o3 : m3,  go1 = q1 ? m3 : o3;

        // activations + packed-sequence masking
        {
            float cn = sigf(gf0 + xg[1].x) * c0
                     + sigf(gi0 + xg[0].x) * tanhfast(gg0 + xg[2].x);
            float hn = sigf(go0 + xg[3].x) * tanhfast(cn);
            bool valid = (t < len0);
            hp0 = valid ? hn : hp0;
            c0  = valid ? cn : c0;
        }
        {
            float cn = sigf(gf1 + xg[1].y) * c1
                     + sigf(gi1 + xg[0].y) * tanhfast(gg1 + xg[2].y);
            float hn = sigf(go1 + xg[3].y) * tanhfast(cn);
            bool valid = (t < len1);
            hp1 = valid ? hn : hp1;
            c1  = valid ? cn : c1;
        }

        // broadcast rounded h to this block's slice in the double buffer
        h0s = __uint_as_float(f2tf32(hp0));
        h1s = __uint_as_float(f2tf32(hp1));
        __stcg((float2*)(hb + (p ^ 1) * (NBD * 256) + sl * 256 + u * 64 + b0),
               make_float2(h0s, h1s));

        __threadfence();
        __syncthreads();
        if (tid == 0)
            asm volatile("st.release.gpu.u32 [%0], %1;"
                         :: "l"(flg + sl * 32), "r"((unsigned)(st + 1)));

        // d_hall stores off the critical path (consumed only by k4)
        d_hall[((size_t)t * BB + b0) * (2 * HH) + dir * HH + j0 + u] = hp0;
        d_hall[((size_t)t * BB + b0 + 1) * (2 * HH) + dir * HH + j0 + u] = hp1;
    }
}

// ---------------- K4: FC + log_softmax (warp per token) ----------------
__global__ void __launch_bounds__(128) k4_fc(
    const float* __restrict__ fcw, const float* __restrict__ fcb)
{
    __shared__ float wsh[CC * 401];
    __shared__ float fbsh[CC];
    __shared__ float hs4[4][2 * HH];
    int tid = threadIdx.x;
    for (int i = tid; i < CC * 2 * HH; i += 128) {
        int c = i / (2 * HH), k = i % (2 * HH);
        wsh[c * 401 + k] = fcw[i];
    }
    if (tid < CC) fbsh[tid] = fcb[tid];
    __syncthreads();

    int w = tid >> 5, lane = tid & 31;
    int tok = blockIdx.x * 4 + w;                    // tok = t*64 + b
    for (int k = lane; k < 2 * HH; k += 32) hs4[w][k] = d_hall[(size_t)tok * (2 * HH) + k];
    __syncwarp();

    float acc = -1e30f;
    if (lane < CC) {
        acc = fbsh[lane];
        const float* wr = wsh + lane * 401;
        #pragma unroll 4
        for (int k = 0; k < 2 * HH; ++k) acc += hs4[w][k] * wr[k];
    }
    float m = acc;
    #pragma unroll
    for (int o = 16; o; o >>= 1) m = fmaxf(m, __shfl_xor_sync(~0u, m, o));
    float e = (lane < CC) ? __expf(acc - m) : 0.f;
    #pragma unroll
    for (int o = 16; o; o >>= 1) e += __shfl_xor_sync(~0u, e, o);
    float lse = m + __logf(e);
    if (lane < CC) {
        int t = tok >> 6, b = tok & 63;
        d_logits[((size_t)b * TT + t) * CC + lane] = acc - lse;
    }
}

// ---------------- K5: CRF NLL, one warp per batch element ----------------
__global__ void __launch_bounds__(32) k5_crf(
    const int* __restrict__ seq_len, const int* __restrict__ target,
    const float* __restrict__ trans, const float* __restrict__ start,
    const float* __restrict__ endsc)
{
    int b = blockIdx.x;
    int lane = threadIdx.x;
    int c = (lane < CC) ? lane : 0;
    int len = seq_len[b];
    const float* L = d_logits + (size_t)b * TT * CC;
    const int* tg = target + (size_t)b * TT;

    float tcol[CC];
    #pragma unroll
    for (int i = 0; i < CC; ++i) tcol[i] = (lane < CC) ? trans[i * CC + c] : 0.f;

    float alpha = (lane < CC) ? (start[c] + L[c]) : -1e30f;

    for (int t = 1; t < len; ++t) {
        float va[CC];
        #pragma unroll
        for (int i = 0; i < CC; ++i)
            va[i] = __shfl_sync(~0u, alpha, i) + tcol[i];
        float m = va[0];
        #pragma unroll
        for (int i = 1; i < CC; ++i) m = fmaxf(m, va[i]);
        float s = 0.f;
        #pragma unroll
        for (int i = 0; i < CC; ++i) s += __expf(va[i] - m);
        float emit = (lane < CC) ? L[t * CC + c] : 0.f;
        float nw = m + __logf(s) + emit;
        alpha = (lane < CC) ? nw : -1e30f;
    }

    float v = (lane < CC) ? (alpha + endsc[c]) : -1e30f;
    float m = v;
    #pragma unroll
    for (int o = 16; o; o >>= 1) m = fmaxf(m, __shfl_xor_sync(~0u, m, o));
    float s = __expf(v - m);
    if (lane >= CC) s = 0.f;
    #pragma unroll
    for (int o = 16; o; o >>= 1) s += __shfl_xor_sync(~0u, s, o);
    float logZ = m + __logf(s);

    float es = 0.f;
    for (int t = lane; t < len; t += 32) es += L[t * CC + tg[t]];
    float ts = 0.f;
    for (int t = lane; t < len - 1; t += 32) ts += trans[tg[t] * CC + tg[t + 1]];
    float g = es + ts;
    #pragma unroll
    for (int o = 16; o; o >>= 1) g += __shfl_xor_sync(~0u, g, o);
    if (lane == 0) {
        float gold = g + start[tg[0]] + endsc[tg[len - 1]];
        d_loss[b] = logZ - gold;
    }
}

// ---------------- K6: mean reduce ----------------
__global__ void __launch_bounds__(64) k6_mean(float* out) {
    __shared__ float sh[64];
    int tid = threadIdx.x;
    sh[tid] = d_loss[tid];
    __syncthreads();
    for (int o = 32; o; o >>= 1) {
        if (tid < o) sh[tid] += sh[tid + o];
        __syncthreads();
    }
    if (tid == 0) out[0] = sh[0] * (1.f / BB);
}

// ---------------- launch ----------------
extern "C" void kernel_launch(void* const* d_in, const int* in_sizes, int n_in,
                              void* d_out, int out_size) {
    const int*   words   = (const int*)d_in[0];
    const int*   seq_len = (const int*)d_in[1];
    const int*   target  = (const int*)d_in[2];
    const float* embed   = (const float*)d_in[3];
    const float* gamma   = (const float*)d_in[4];
    const float* beta    = (const float*)d_in[5];
    const float* wihf    = (const float*)d_in[6];
    const float* whhf    = (const float*)d_in[7];
    const float* bf      = (const float*)d_in[8];
    const float* wihb    = (const float*)d_in[9];
    const float* whhb    = (const float*)d_in[10];
    const float* bb      = (const float*)d_in[11];
    const float* fcw     = (const float*)d_in[12];
    const float* fcb     = (const float*)d_in[13];
    const float* trans   = (const float*)d_in[14];
    const float* startsc = (const float*)d_in[15];
    const float* endsc   = (const float*)d_in[16];
    float* out = (float*)d_out;

    size_t hsmem = (size_t)HH * 72 * sizeof(float);   // 57600 B
    cudaFuncSetAttribute(k3_lstm, cudaFuncAttributeMaxDynamicSharedMemorySize,
                         (int)hsmem);

    k0_init<<<1, 256>>>();
    k1_embed_ln<<<TT * BB / 8, 256>>>(words, embed, gamma, beta);
    {
        dim3 g(2 * G4 / 64, TT * BB / 128);   // 25 x 256
        k2_gemm<<<g, 256>>>(wihf, wihb, bf, bb);
    }
    k3_lstm<<<2 * NBD, 128, hsmem>>>(whhf, whhb, seq_len);
    k4_fc<<<TT * BB / 4, 128>>>(fcw, fcb);
    k5_crf<<<BB, 32>>>(seq_len, target, trans, startsc, endsc);
    k6_mean<<<1, 64>>>(out);
}

// round 7
// speedup vs baseline: 1.7681x; 1.2539x over previous
#include <cuda_runtime.h>
#include <cuda_bf16.h>
#include <math.h>

#define TT 512
#define BB 64
#define EE 256
#define HH 200
#define G4 800
#define CC 20
#define NBD 50   // blocks per direction in LSTM kernel
#define HSL 4    // h-units per block (HH / NBD)
#define KT 25    // k-tiles of 8 in HH=200

typedef unsigned long long ull;
typedef unsigned int uint;

// ---------------- device scratch (no allocations allowed) ----------------
__device__ float d_x[TT * BB * EE];            // LN'd embeddings, [tok=t*64+b][e]
__device__ float d_G[2 * TT * G4 * BB];        // gates_x [dir][t][gate_row][b]
__device__ float d_hall[TT * BB * 2 * HH];     // h states [t][b][dir*H + j]
__device__ uint  d_hbufh[2 * 2 * NBD * 128];   // h dbuf, packed bf16x2 [dir][ph][slice][...]
__device__ float d_logits[BB * TT * CC];       // log_softmax outputs [b][t][c]
__device__ float d_loss[BB];
__device__ unsigned d_flagsp[2][NBD][32];      // flags spread 128B apart

__device__ __forceinline__ uint f2tf32(float v) {
    uint r;
    asm("cvt.rna.tf32.f32 %0, %1;" : "=r"(r) : "f"(v));
    return r;
}
__device__ __forceinline__ float sigf(float x)  { return 1.f / (1.f + __expf(-x)); }
__device__ __forceinline__ float tanhfast(float x) { return 1.f - 2.f / (__expf(2.f * x) + 1.f); }

#define MMA_TF32(ACC, A, B0, B1)                                           \
    asm volatile(                                                          \
        "mma.sync.aligned.m16n8k8.row.col.f32.tf32.tf32.f32 "              \
        "{%0,%1,%2,%3}, {%4,%5,%6,%7}, {%8,%9}, {%0,%1,%2,%3};"            \
        : "+f"((ACC)[0]), "+f"((ACC)[1]), "+f"((ACC)[2]), "+f"((ACC)[3])   \
        : "r"((A)[0]), "r"((A)[1]), "r"((A)[2]), "r"((A)[3]),              \
          "r"(B0), "r"(B1))

// ---------------- K0: init ----------------
__global__ void k0_init() {
    int tid = threadIdx.x;
    for (int i = tid; i < 2 * 2 * NBD * 128; i += 256) d_hbufh[i] = 0u;
    for (int i = tid; i < 2 * NBD * 32; i += 256) ((unsigned*)d_flagsp)[i] = 0u;
}

// ---------------- K1: embedding + LayerNorm (warp per token) ----------------
__global__ void __launch_bounds__(256) k1_embed_ln(
    const int* __restrict__ words, const float* __restrict__ embed,
    const float* __restrict__ gamma, const float* __restrict__ beta)
{
    int wid = threadIdx.x >> 5, lane = threadIdx.x & 31;
    int tok = blockIdx.x * 8 + wid;          // tok = t*64 + b
    int t = tok >> 6, b = tok & 63;
    int word = words[b * TT + t];
    const float4* src = (const float4*)(embed + (size_t)word * EE);
    float4 v0 = src[lane * 2], v1 = src[lane * 2 + 1];
    float s = v0.x + v0.y + v0.z + v0.w + v1.x + v1.y + v1.z + v1.w;
    float q = v0.x*v0.x + v0.y*v0.y + v0.z*v0.z + v0.w*v0.w
            + v1.x*v1.x + v1.y*v1.y + v1.z*v1.z + v1.w*v1.w;
    #pragma unroll
    for (int o = 16; o; o >>= 1) {
        s += __shfl_xor_sync(~0u, s, o);
        q += __shfl_xor_sync(~0u, q, o);
    }
    float mu  = s * (1.f / EE);
    float var = q * (1.f / EE) - mu * mu;
    float rs  = rsqrtf(var + 1e-5f);
    const float4* g4 = (const float4*)gamma;
    const float4* bt4 = (const float4*)beta;
    float4 ga = g4[lane*2], gb = g4[lane*2+1];
    float4 ba = bt4[lane*2], bb = bt4[lane*2+1];
    float4 o0, o1;
    o0.x = (v0.x-mu)*rs*ga.x + ba.x;  o0.y = (v0.y-mu)*rs*ga.y + ba.y;
    o0.z = (v0.z-mu)*rs*ga.z + ba.z;  o0.w = (v0.w-mu)*rs*ga.w + ba.w;
    o1.x = (v1.x-mu)*rs*gb.x + bb.x;  o1.y = (v1.y-mu)*rs*gb.y + bb.y;
    o1.z = (v1.z-mu)*rs*gb.z + bb.z;  o1.w = (v1.w-mu)*rs*gb.w + bb.w;
    float4* dst = (float4*)(d_x + (size_t)tok * EE);
    dst[lane*2] = o0; dst[lane*2+1] = o1;
}

// ---------------- K2: tf32 tensor-core GEMM  gates_x = X @ W_ih^T + b ----------------
__global__ void __launch_bounds__(256) k2_gemm(
    const float* __restrict__ wihf, const float* __restrict__ wihb,
    const float* __restrict__ bf,   const float* __restrict__ bbias)
{
    __shared__ uint As[128 * 20];   // [m][k] stride 20 (tf32 bits)
    __shared__ uint Bs[64 * 20];    // [n][k] stride 20 (tf32 bits)

    int tid = threadIdx.x;
    int m0 = blockIdx.y * 128, n0 = blockIdx.x * 64;
    int wid = tid >> 5, lane = tid & 31;
    int wm = wid & 3, wn = wid >> 2;            // warp grid 4 x 2
    int gid = lane >> 2, ctid = lane & 3;

    float acc[2][4][4];
    #pragma unroll
    for (int mi = 0; mi < 2; ++mi)
        #pragma unroll
        for (int ni = 0; ni < 4; ++ni)
            #pragma unroll
            for (int r = 0; r < 4; ++r) acc[mi][ni][r] = 0.f;

    for (int k0 = 0; k0 < EE; k0 += 16) {
        #pragma unroll
        for (int i = 0; i < 2; ++i) {
            int j = tid + i * 256;
            int row = j >> 2, kq = (j & 3) * 4;
            float4 v = *(const float4*)(d_x + (size_t)(m0 + row) * EE + k0 + kq);
            uint* dst = As + row * 20 + kq;
            dst[0] = f2tf32(v.x); dst[1] = f2tf32(v.y);
            dst[2] = f2tf32(v.z); dst[3] = f2tf32(v.w);
        }
        {
            int row = tid >> 2, kq = (tid & 3) * 4;
            int nglob = n0 + row;
            const float* wrow = (nglob < G4) ? (wihf + (size_t)nglob * EE)
                                             : (wihb + (size_t)(nglob - G4) * EE);
            float4 v = *(const float4*)(wrow + k0 + kq);
            uint* dst = Bs + row * 20 + kq;
            dst[0] = f2tf32(v.x); dst[1] = f2tf32(v.y);
            dst[2] = f2tf32(v.z); dst[3] = f2tf32(v.w);
        }
        __syncthreads();

        #pragma unroll
        for (int k8 = 0; k8 < 16; k8 += 8) {
            uint afr[2][4], bfr[4][2];
            #pragma unroll
            for (int mi = 0; mi < 2; ++mi) {
                int mb = wm * 32 + mi * 16;
                const uint* ap = As + (mb + gid) * 20 + k8 + ctid;
                afr[mi][0] = ap[0];
                afr[mi][1] = ap[8 * 20];
                afr[mi][2] = ap[4];
                afr[mi][3] = ap[8 * 20 + 4];
            }
            #pragma unroll
            for (int ni = 0; ni < 4; ++ni) {
                int nb = wn * 32 + ni * 8;
                const uint* bp = Bs + (nb + gid) * 20 + k8 + ctid;
                bfr[ni][0] = bp[0];
                bfr[ni][1] = bp[4];
            }
            #pragma unroll
            for (int mi = 0; mi < 2; ++mi)
                #pragma unroll
                for (int ni = 0; ni < 4; ++ni)
                    MMA_TF32(acc[mi][ni], afr[mi], bfr[ni][0], bfr[ni][1]);
        }
        __syncthreads();
    }

    #pragma unroll
    for (int mi = 0; mi < 2; ++mi)
        #pragma unroll
        for (int ni = 0; ni < 4; ++ni)
            #pragma unroll
            for (int r = 0; r < 4; ++r) {
                int m = m0 + wm * 32 + mi * 16 + gid + (r >> 1) * 8;
                int n = n0 + wn * 32 + ni * 8 + 2 * ctid + (r & 1);
                int dir = (n >= G4) ? 1 : 0;
                int rr = n - dir * G4;
                float bias = dir ? bbias[rr] : bf[rr];
                int t = m >> 6, b = m & 63;
                d_G[(size_t)dir * (TT * G4 * BB) + ((size_t)t * G4 + rr) * BB + b]
                    = acc[mi][ni][r] + bias;
            }
}

// ---------------- K3: persistent BiLSTM, tensor-core recurrence ----------------
// bf16 h exchange, staged d_hall flush every 4 steps, tid0-only release fence.
__global__ void __launch_bounds__(128, 1) k3_lstm(
    const float* __restrict__ whhf, const float* __restrict__ whhb,
    const int* __restrict__ seq_len)
{
    extern __shared__ float dyn[];
    float* hsh = dyn;                         // [HH][72] f32 mma tile (57600 B)
    float* hstage = dyn + HH * 72;            // [4][64][4] d_hall stage (4096 B)

    int tid = threadIdx.x;
    int dir = blockIdx.x / NBD;
    int sl  = blockIdx.x % NBD;
    int j0  = sl * HSL;
    const float* whh = dir ? whhb : whhf;

    int wid = tid >> 5, lane = tid & 31;
    int gid = lane >> 2, ctid = lane & 3;
    int u   = gid & 3;            // local hidden unit 0..3
    int q1  = gid >> 2;           // 0: rows {i,g}; 1: rows {f,o}
    int bnw = wid * 16;           // warp batch base
    int b0  = bnw + q1 * 8 + 2 * ctid;   // this thread's batch pair (b0, b0+1)

    // persistent A fragments: W rows r16 = q*4+u, cols k (tf32)
    uint aw[KT][4];
    {
        int rowA = q1 * HH + j0 + u;         // mma row gid   -> gate q1
        int rowB = (q1 + 2) * HH + j0 + u;   // mma row gid+8 -> gate q1+2
        #pragma unroll
        for (int kt = 0; kt < KT; ++kt) {
            int k0 = kt * 8;
            aw[kt][0] = f2tf32(whh[(size_t)rowA * HH + k0 + ctid]);
            aw[kt][1] = f2tf32(whh[(size_t)rowB * HH + k0 + ctid]);
            aw[kt][2] = f2tf32(whh[(size_t)rowA * HH + k0 + ctid + 4]);
            aw[kt][3] = f2tf32(whh[(size_t)rowB * HH + k0 + ctid + 4]);
        }
    }

    int len0 = seq_len[b0], len1 = seq_len[b0 + 1];
    float c0 = 0.f, c1 = 0.f, hp0 = 0.f, hp1 = 0.f;
    float h0s = 0.f, h1s = 0.f;   // bf16-rounded h (what every block sees)

    const float* G = d_G + (size_t)dir * (TT * G4 * BB);
    uint* hb = d_hbufh + dir * (2 * NBD * 128);
    unsigned* flg = &d_flagsp[dir][0][0];   // stride 32 u32 per producer

    // loader assignment: 2 threads per foreign slice, 16 uint4 chunks each
    int ls2 = tid >> 1, lhalf = tid & 1;
    int lslice = ls2 + (ls2 >= sl ? 1 : 0);
    bool loader = (tid < 2 * (NBD - 1));

    // gx offsets (gates i,f,g,o) for this thread's unit/batch-pair
    size_t goff[4];
    #pragma unroll
    for (int q = 0; q < 4; ++q)
        goff[q] = ((size_t)(q * HH + j0 + u)) * BB + b0;

    for (int st = 0; st < TT; ++st) {
        int t = dir ? (TT - 1 - st) : st;
        int p = st & 1;
        const float* Gt = G + (size_t)t * G4 * BB;

        // prefetch gx (h-independent) to overlap the flag wait
        float2 xg[4];
        #pragma unroll
        for (int q = 0; q < 4; ++q) xg[q] = *(const float2*)(Gt + goff[q]);

        // own slice: scatter rounded h directly from registers
        *(float2*)&hsh[(j0 + u) * 72 + b0] = make_float2(h0s, h1s);

        // foreign slices: poll producer flag, load bf16 slice, convert+scatter
        if (loader) {
            unsigned v;
            const unsigned* fp = flg + lslice * 32;
            do {
                asm volatile("ld.acquire.gpu.u32 %0, [%1];" : "=r"(v) : "l"(fp));
            } while (v < (unsigned)st);
            const uint4* src = (const uint4*)(hb + p * (NBD * 128) + lslice * 128);
            float* rowbase = hsh + (4 * lslice) * 72;
            #pragma unroll 4
            for (int j = 0; j < 16; ++j) {
                int c = j * 2 + lhalf;            // uint4 chunk 0..31
                uint4 pk = __ldcg(src + c);
                int uu = c >> 3, bb = (c & 7) * 8;
                float* dst = rowbase + uu * 72 + bb;
                dst[0] = __uint_as_float(pk.x << 16);
                dst[1] = __uint_as_float(pk.x & 0xFFFF0000u);
                dst[2] = __uint_as_float(pk.y << 16);
                dst[3] = __uint_as_float(pk.y & 0xFFFF0000u);
                dst[4] = __uint_as_float(pk.z << 16);
                dst[5] = __uint_as_float(pk.z & 0xFFFF0000u);
                dst[6] = __uint_as_float(pk.w << 16);
                dst[7] = __uint_as_float(pk.w & 0xFFFF0000u);
            }
        }
        __syncthreads();

        // gates(16 x 64) = W @ h  via 2 n-tiles x 25 k-tiles of m16n8k8
        float acc0[4] = {0.f, 0.f, 0.f, 0.f};
        float acc1[4] = {0.f, 0.f, 0.f, 0.f};
        #pragma unroll
        for (int kt = 0; kt < KT; ++kt) {
            const float* hk = hsh + (kt * 8 + ctid) * 72;
            uint b00 = __float_as_uint(hk[bnw + gid]);
            uint b01 = __float_as_uint(hk[4 * 72 + bnw + gid]);
            uint b10 = __float_as_uint(hk[bnw + 8 + gid]);
            uint b11 = __float_as_uint(hk[4 * 72 + bnw + 8 + gid]);
            MMA_TF32(acc0, aw[kt], b00, b01);
            MMA_TF32(acc1, aw[kt], b10, b11);
        }

        // exchange gate pairs with partner (lane ^ 16)
        float s0 = q1 ? acc0[0] : acc1[0];
        float s1 = q1 ? acc0[1] : acc1[1];
        float s2 = q1 ? acc0[2] : acc1[2];
        float s3 = q1 ? acc0[3] : acc1[3];
        float o0 = __shfl_xor_sync(~0u, s0, 16);
        float o1 = __shfl_xor_sync(~0u, s1, 16);
        float o2 = __shfl_xor_sync(~0u, s2, 16);
        float o3 = __shfl_xor_sync(~0u, s3, 16);
        float m0 = q1 ? acc1[0] : acc0[0];
        float m1 = q1 ? acc1[1] : acc0[1];
        float m2 = q1 ? acc1[2] : acc0[2];
        float m3 = q1 ? acc1[3] : acc0[3];
        float gi0 = q1 ? o0 : m0,  gf0 = q1 ? m0 : o0;
        float gg0 = q1 ? o2 : m2,  go0 = q1 ? m2 : o2;
        float gi1 = q1 ? o1 : m1,  gf1 = q1 ? m1 : o1;
        float gg1 = q1 ? o3 : m3,  go1 = q1 ? m3 : o3;

        // activations + packed-sequence masking
        {
            float cn = sigf(gf0 + xg[1].x) * c0
                     + sigf(gi0 + xg[0].x) * tanhfast(gg0 + xg[2].x);
            float hn = sigf(go0 + xg[3].x) * tanhfast(cn);
            bool valid = (t < len0);
            hp0 = valid ? hn : hp0;
            c0  = valid ? cn : c0;
        }
        {
            float cn = sigf(gf1 + xg[1].y) * c1
                     + sigf(gi1 + xg[0].y) * tanhfast(gg1 + xg[2].y);
            float hn = sigf(go1 + xg[3].y) * tanhfast(cn);
            bool valid = (t < len1);
            hp1 = valid ? hn : hp1;
            c1  = valid ? cn : c1;
        }

        // pack bf16x2 broadcast; local copy uses the SAME rounded bits
        uint pk;
        asm("cvt.rn.bf16x2.f32 %0, %1, %2;" : "=r"(pk) : "f"(hp1), "f"(hp0));
        h0s = __uint_as_float(pk << 16);
        h1s = __uint_as_float(pk & 0xFFFF0000u);
        __stcg(hb + (p ^ 1) * (NBD * 128) + sl * 128 + u * 32 + (b0 >> 1), pk);

        // stage full-precision h for d_hall (flushed every 4 steps)
        hstage[((st & 3) * 64 + b0) * 4 + u] = hp0;
        hstage[((st & 3) * 64 + b0 + 1) * 4 + u] = hp1;

        __syncthreads();
        if (tid == 0) {
            asm volatile("fence.acq_rel.gpu;" ::: "memory");
            asm volatile("st.relaxed.gpu.u32 [%0], %1;"
                         :: "l"(flg + sl * 32), "r"((unsigned)(st + 1)) : "memory");
        }

        // coalesced d_hall flush, off the critical path
        if ((st & 3) == 3) {
            #pragma unroll
            for (int rep = 0; rep < 2; ++rep) {
                int idx = tid + rep * 128;
                int tf = idx >> 6, b = idx & 63;
                float4 hv = *(const float4*)&hstage[(tf * 64 + b) * 4];
                int tt = dir ? (TT - 1 - (st - 3 + tf)) : (st - 3 + tf);
                *(float4*)&d_hall[((size_t)tt * BB + b) * (2 * HH) + dir * HH + j0] = hv;
            }
        }
    }
}

// ---------------- K4: FC + log_softmax (warp per token) ----------------
__global__ void __launch_bounds__(128) k4_fc(
    const float* __restrict__ fcw, const float* __restrict__ fcb)
{
    __shared__ float wsh[CC * 401];
    __shared__ float fbsh[CC];
    __shared__ float hs4[4][2 * HH];
    int tid = threadIdx.x;
    for (int i = tid; i < CC * 2 * HH; i += 128) {
        int c = i / (2 * HH), k = i % (2 * HH);
        wsh[c * 401 + k] = fcw[i];
    }
    if (tid < CC) fbsh[tid] = fcb[tid];
    __syncthreads();

    int w = tid >> 5, lane = tid & 31;
    int tok = blockIdx.x * 4 + w;                    // tok = t*64 + b
    for (int k = lane; k < 2 * HH; k += 32) hs4[w][k] = d_hall[(size_t)tok * (2 * HH) + k];
    __syncwarp();

    float acc = -1e30f;
    if (lane < CC) {
        acc = fbsh[lane];
        const float* wr = wsh + lane * 401;
        #pragma unroll 4
        for (int k = 0; k < 2 * HH; ++k) acc += hs4[w][k] * wr[k];
    }
    float m = acc;
    #pragma unroll
    for (int o = 16; o; o >>= 1) m = fmaxf(m, __shfl_xor_sync(~0u, m, o));
    float e = (lane < CC) ? __expf(acc - m) : 0.f;
    #pragma unroll
    for (int o = 16; o; o >>= 1) e += __shfl_xor_sync(~0u, e, o);
    float lse = m + __logf(e);
    if (lane < CC) {
        int t = tok >> 6, b = tok & 63;
        d_logits[((size_t)b * TT + t) * CC + lane] = acc - lse;
    }
}

// ---------------- K5: CRF NLL, one warp per batch element ----------------
__global__ void __launch_bounds__(32) k5_crf(
    const int* __restrict__ seq_len, const int* __restrict__ target,
    const float* __restrict__ trans, const float* __restrict__ start,
    const float* __restrict__ endsc)
{
    int b = blockIdx.x;
    int lane = threadIdx.x;
    int c = (lane < CC) ? lane : 0;
    int len = seq_len[b];
    const float* L = d_logits + (size_t)b * TT * CC;
    const int* tg = target + (size_t)b * TT;

    float tcol[CC];
    #pragma unroll
    for (int i = 0; i < CC; ++i) tcol[i] = (lane < CC) ? trans[i * CC + c] : 0.f;

    float alpha = (lane < CC) ? (start[c] + L[c]) : -1e30f;

    for (int t = 1; t < len; ++t) {
        float va[CC];
        #pragma unroll
        for (int i = 0; i < CC; ++i)
            va[i] = __shfl_sync(~0u, alpha, i) + tcol[i];
        float m = va[0];
        #pragma unroll
        for (int i = 1; i < CC; ++i) m = fmaxf(m, va[i]);
        float s = 0.f;
        #pragma unroll
        for (int i = 0; i < CC; ++i) s += __expf(va[i] - m);
        float emit = (lane < CC) ? L[t * CC + c] : 0.f;
        float nw = m + __logf(s) + emit;
        alpha = (lane < CC) ? nw : -1e30f;
    }

    float v = (lane < CC) ? (alpha + endsc[c]) : -1e30f;
    float m = v;
    #pragma unroll
    for (int o = 16; o; o >>= 1) m = fmaxf(m, __shfl_xor_sync(~0u, m, o));
    float s = __expf(v - m);
    if (lane >= CC) s = 0.f;
    #pragma unroll
    for (int o = 16; o; o >>= 1) s += __shfl_xor_sync(~0u, s, o);
    float logZ = m + __logf(s);

    float es = 0.f;
    for (int t = lane; t < len; t += 32) es += L[t * CC + tg[t]];
    float ts = 0.f;
    for (int t = lane; t < len - 1; t += 32) ts += trans[tg[t] * CC + tg[t + 1]];
    float g = es + ts;
    #pragma unroll
    for (int o = 16; o; o >>= 1) g += __shfl_xor_sync(~0u, g, o);
    if (lane == 0) {
        float gold = g + start[tg[0]] + endsc[tg[len - 1]];
        d_loss[b] = logZ - gold;
    }
}

// ---------------- K6: mean reduce ----------------
__global__ void __launch_bounds__(64) k6_mean(float* out) {
    __shared__ float sh[64];
    int tid = threadIdx.x;
    sh[tid] = d_loss[tid];
    __syncthreads();
    for (int o = 32; o; o >>= 1) {
        if (tid < o) sh[tid] += sh[tid + o];
        __syncthreads();
    }
    if (tid == 0) out[0] = sh[0] * (1.f / BB);
}

// ---------------- launch ----------------
extern "C" void kernel_launch(void* const* d_in, const int* in_sizes, int n_in,
                              void* d_out, int out_size) {
    const int*   words   = (const int*)d_in[0];
    const int*   seq_len = (const int*)d_in[1];
    const int*   target  = (const int*)d_in[2];
    const float* embed   = (const float*)d_in[3];
    const float* gamma   = (const float*)d_in[4];
    const float* beta    = (const float*)d_in[5];
    const float* wihf    = (const float*)d_in[6];
    const float* whhf    = (const float*)d_in[7];
    const float* bf      = (const float*)d_in[8];
    const float* wihb    = (const float*)d_in[9];
    const float* whhb    = (const float*)d_in[10];
    const float* bb      = (const float*)d_in[11];
    const float* fcw     = (const float*)d_in[12];
    const float* fcb     = (const float*)d_in[13];
    const float* trans   = (const float*)d_in[14];
    const float* startsc = (const float*)d_in[15];
    const float* endsc   = (const float*)d_in[16];
    float* out = (float*)d_out;

    size_t hsmem = (size_t)(HH * 72 + 4 * 64 * 4) * sizeof(float);   // 61696 B
    cudaFuncSetAttribute(k3_lstm, cudaFuncAttributeMaxDynamicSharedMemorySize,
                         (int)hsmem);

    k0_init<<<1, 256>>>();
    k1_embed_ln<<<TT * BB / 8, 256>>>(words, embed, gamma, beta);
    {
        dim3 g(2 * G4 / 64, TT * BB / 128);   // 25 x 256
        k2_gemm<<<g, 256>>>(wihf, wihb, bf, bb);
    }
    k3_lstm<<<2 * NBD, 128, hsmem>>>(whhf, whhb, seq_len);
    k4_fc<<<TT * BB / 4, 128>>>(fcw, fcb);
    k5_crf<<<BB, 32>>>(seq_len, target, trans, startsc, endsc);
    k6_mean<<<1, 64>>>(out);
}

// round 8
// speedup vs baseline: 2.2195x; 1.2553x over previous
#include <cuda_runtime.h>
#include <cuda_bf16.h>
#include <math.h>

#define TT 512
#define BB 64
#define EE 256
#define HH 200
#define G4 800
#define CC 20
#define NBD 50   // blocks per direction in LSTM kernel
#define HSL 4    // h-units per block (HH / NBD)
#define KT3 13   // k16-tiles covering HH=200 (pad to 208)

typedef unsigned long long ull;
typedef unsigned int uint;

// ---------------- device scratch (no allocations allowed) ----------------
__device__ float d_x[TT * BB * EE];            // LN'd embeddings, [tok=t*64+b][e]
__device__ float d_G[2 * TT * G4 * BB];        // gates_x [dir][t][gate_row][b]
__device__ float d_hall[TT * BB * 2 * HH];     // h states [t][b][dir*H + j]
__device__ uint  d_hbufh[2 * 2 * NBD * 128];   // h dbuf, packed bf16x2 [dir][ph][slice][...]
__device__ float d_logits[BB * TT * CC];       // log_softmax outputs [b][t][c]
__device__ float d_loss[BB];
__device__ unsigned d_flagsp[2][NBD][32];      // flags spread 128B apart

__device__ __forceinline__ uint pkbf(float lo, float hi) {
    uint r;
    asm("cvt.rn.bf16x2.f32 %0, %1, %2;" : "=r"(r) : "f"(hi), "f"(lo));
    return r;
}
__device__ __forceinline__ float sigf(float x)  { return 1.f / (1.f + __expf(-x)); }
__device__ __forceinline__ float tanhfast(float x) { return 1.f - 2.f / (__expf(2.f * x) + 1.f); }

#define MMA_BF16(ACC, A, B0, B1)                                           \
    asm volatile(                                                          \
        "mma.sync.aligned.m16n8k16.row.col.f32.bf16.bf16.f32 "             \
        "{%0,%1,%2,%3}, {%4,%5,%6,%7}, {%8,%9}, {%0,%1,%2,%3};"            \
        : "+f"((ACC)[0]), "+f"((ACC)[1]), "+f"((ACC)[2]), "+f"((ACC)[3])   \
        : "r"((A)[0]), "r"((A)[1]), "r"((A)[2]), "r"((A)[3]),              \
          "r"(B0), "r"(B1))

// ---------------- K0: init ----------------
__global__ void k0_init() {
    int tid = threadIdx.x;
    for (int i = tid; i < 2 * 2 * NBD * 128; i += 256) d_hbufh[i] = 0u;
    for (int i = tid; i < 2 * NBD * 32; i += 256) ((unsigned*)d_flagsp)[i] = 0u;
}

// ---------------- K1: embedding + LayerNorm (warp per token) ----------------
__global__ void __launch_bounds__(256) k1_embed_ln(
    const int* __restrict__ words, const float* __restrict__ embed,
    const float* __restrict__ gamma, const float* __restrict__ beta)
{
    int wid = threadIdx.x >> 5, lane = threadIdx.x & 31;
    int tok = blockIdx.x * 8 + wid;          // tok = t*64 + b
    int t = tok >> 6, b = tok & 63;
    int word = words[b * TT + t];
    const float4* src = (const float4*)(embed + (size_t)word * EE);
    float4 v0 = src[lane * 2], v1 = src[lane * 2 + 1];
    float s = v0.x + v0.y + v0.z + v0.w + v1.x + v1.y + v1.z + v1.w;
    float q = v0.x*v0.x + v0.y*v0.y + v0.z*v0.z + v0.w*v0.w
            + v1.x*v1.x + v1.y*v1.y + v1.z*v1.z + v1.w*v1.w;
    #pragma unroll
    for (int o = 16; o; o >>= 1) {
        s += __shfl_xor_sync(~0u, s, o);
        q += __shfl_xor_sync(~0u, q, o);
    }
    float mu  = s * (1.f / EE);
    float var = q * (1.f / EE) - mu * mu;
    float rs  = rsqrtf(var + 1e-5f);
    const float4* g4 = (const float4*)gamma;
    const float4* bt4 = (const float4*)beta;
    float4 ga = g4[lane*2], gb = g4[lane*2+1];
    float4 ba = bt4[lane*2], bb = bt4[lane*2+1];
    float4 o0, o1;
    o0.x = (v0.x-mu)*rs*ga.x + ba.x;  o0.y = (v0.y-mu)*rs*ga.y + ba.y;
    o0.z = (v0.z-mu)*rs*ga.z + ba.z;  o0.w = (v0.w-mu)*rs*ga.w + ba.w;
    o1.x = (v1.x-mu)*rs*gb.x + bb.x;  o1.y = (v1.y-mu)*rs*gb.y + bb.y;
    o1.z = (v1.z-mu)*rs*gb.z + bb.z;  o1.w = (v1.w-mu)*rs*gb.w + bb.w;
    float4* dst = (float4*)(d_x + (size_t)tok * EE);
    dst[lane*2] = o0; dst[lane*2+1] = o1;
}

// ---------------- K2: bf16 tensor-core GEMM  gates_x = X @ W_ih^T + b ----------------
// C[32768,1600]. BM=128, BN=64, BK=16, 256 threads = 8 warps (4m x 2n),
// warp tile 32x32 = 2 (m16) x 4 (n8) tiles, m16n8k16 bf16.
__global__ void __launch_bounds__(256) k2_gemm(
    const float* __restrict__ wihf, const float* __restrict__ wihb,
    const float* __restrict__ bf,   const float* __restrict__ bbias)
{
    __shared__ uint As2[128 * 12];   // [m][k/2] bf16x2, stride 12 (8 data + 4 pad)
    __shared__ uint Bs2[64 * 12];

    int tid = threadIdx.x;
    int m0 = blockIdx.y * 128, n0 = blockIdx.x * 64;
    int wid = tid >> 5, lane = tid & 31;
    int wm = wid & 3, wn = wid >> 2;            // warp grid 4 x 2
    int gid = lane >> 2, ctid = lane & 3;

    float acc[2][4][4];
    #pragma unroll
    for (int mi = 0; mi < 2; ++mi)
        #pragma unroll
        for (int ni = 0; ni < 4; ++ni)
            #pragma unroll
            for (int r = 0; r < 4; ++r) acc[mi][ni][r] = 0.f;

    for (int k0 = 0; k0 < EE; k0 += 16) {
        // A tile: 128x16 floats = 512 float4; 2 per thread -> bf16x2 pairs
        #pragma unroll
        for (int i = 0; i < 2; ++i) {
            int j = tid + i * 256;
            int row = j >> 2, kq = (j & 3) * 4;
            float4 v = *(const float4*)(d_x + (size_t)(m0 + row) * EE + k0 + kq);
            uint* dst = As2 + row * 12 + (j & 3) * 2;
            dst[0] = pkbf(v.x, v.y);
            dst[1] = pkbf(v.z, v.w);
        }
        // B tile: 64x16 = 256 float4, 1 per thread
        {
            int row = tid >> 2, kq = (tid & 3) * 4;
            int nglob = n0 + row;
            const float* wrow = (nglob < G4) ? (wihf + (size_t)nglob * EE)
                                             : (wihb + (size_t)(nglob - G4) * EE);
            float4 v = *(const float4*)(wrow + k0 + kq);
            uint* dst = Bs2 + row * 12 + (tid & 3) * 2;
            dst[0] = pkbf(v.x, v.y);
            dst[1] = pkbf(v.z, v.w);
        }
        __syncthreads();

        uint afr[2][4], bfr[4][2];
        #pragma unroll
        for (int mi = 0; mi < 2; ++mi) {
            int mb = wm * 32 + mi * 16;
            const uint* ap = As2 + (mb + gid) * 12 + ctid;
            afr[mi][0] = ap[0];
            afr[mi][1] = ap[8 * 12];
            afr[mi][2] = ap[4];
            afr[mi][3] = ap[8 * 12 + 4];
        }
        #pragma unroll
        for (int ni = 0; ni < 4; ++ni) {
            int nb = wn * 32 + ni * 8;
            const uint* bp = Bs2 + (nb + gid) * 12 + ctid;
            bfr[ni][0] = bp[0];
            bfr[ni][1] = bp[4];
        }
        #pragma unroll
        for (int mi = 0; mi < 2; ++mi)
            #pragma unroll
            for (int ni = 0; ni < 4; ++ni)
                MMA_BF16(acc[mi][ni], afr[mi], bfr[ni][0], bfr[ni][1]);
        __syncthreads();
    }

    #pragma unroll
    for (int mi = 0; mi < 2; ++mi)
        #pragma unroll
        for (int ni = 0; ni < 4; ++ni)
            #pragma unroll
            for (int r = 0; r < 4; ++r) {
                int m = m0 + wm * 32 + mi * 16 + gid + (r >> 1) * 8;
                int n = n0 + wn * 32 + ni * 8 + 2 * ctid + (r & 1);
                int dir = (n >= G4) ? 1 : 0;
                int rr = n - dir * G4;
                float bias = dir ? bbias[rr] : bf[rr];
                int t = m >> 6, b = m & 63;
                d_G[(size_t)dir * (TT * G4 * BB) + ((size_t)t * G4 + rr) * BB + b]
                    = acc[mi][ni][r] + bias;
            }
}

// ---------------- K3: persistent BiLSTM, bf16 tensor-core recurrence ----------------
// 100 blocks (50/dir), 128 threads. h stays packed bf16x2 end-to-end; loaders
// repack k-pairs via PRMT. W_hh bf16 A-frags resident in registers (52 regs).
__global__ void __launch_bounds__(128, 1) k3_lstm(
    const float* __restrict__ whhf, const float* __restrict__ whhb,
    const int* __restrict__ seq_len)
{
    extern __shared__ uint dynu[];
    uint* hsh2 = dynu;                        // [104][72] bf16x2 (k-pair, n) 29952 B
    float* hstage = (float*)(dynu + 104 * 72); // [4][64][4] d_hall stage (4096 B)

    int tid = threadIdx.x;
    int dir = blockIdx.x / NBD;
    int sl  = blockIdx.x % NBD;
    int j0  = sl * HSL;
    const float* whh = dir ? whhb : whhf;

    int wid = tid >> 5, lane = tid & 31;
    int gid = lane >> 2, ctid = lane & 3;
    int u   = gid & 3;            // local hidden unit 0..3
    int q1  = gid >> 2;           // 0: rows {i,g}; 1: rows {f,o}
    int bnw = wid * 16;           // warp batch base
    int b0  = bnw + q1 * 8 + 2 * ctid;   // this thread's batch pair (b0, b0+1)

    // persistent bf16 A fragments (k16 tiles; zero-pad k>=200)
    uint aw[KT3][4];
    {
        int rowA = q1 * HH + j0 + u;         // mma row gid   -> gate q1
        int rowB = (q1 + 2) * HH + j0 + u;   // mma row gid+8 -> gate q1+2
        #pragma unroll
        for (int kt = 0; kt < KT3; ++kt) {
            int kA = kt * 16 + 2 * ctid;
            int kC = kA + 8;
            float a0 = whh[(size_t)rowA * HH + kA];
            float a1 = whh[(size_t)rowA * HH + kA + 1];
            float b0v = whh[(size_t)rowB * HH + kA];
            float b1v = whh[(size_t)rowB * HH + kA + 1];
            float a2 = (kC < HH) ? whh[(size_t)rowA * HH + kC] : 0.f;
            float a3 = (kC + 1 < HH) ? whh[(size_t)rowA * HH + kC + 1] : 0.f;
            float b2v = (kC < HH) ? whh[(size_t)rowB * HH + kC] : 0.f;
            float b3v = (kC + 1 < HH) ? whh[(size_t)rowB * HH + kC + 1] : 0.f;
            aw[kt][0] = pkbf(a0, a1);
            aw[kt][1] = pkbf(b0v, b1v);
            aw[kt][2] = pkbf(a2, a3);
            aw[kt][3] = pkbf(b2v, b3v);
        }
    }

    // zero the pad rows 100..103 (k 200..207) once
    for (int i = tid; i < 4 * 72; i += 128) hsh2[100 * 72 + i] = 0u;

    int len0 = seq_len[b0], len1 = seq_len[b0 + 1];
    float c0 = 0.f, c1 = 0.f, hp0 = 0.f, hp1 = 0.f;
    uint pk = 0u;                 // packed bf16x2 (hp0 lo, hp1 hi)

    const float* G = d_G + (size_t)dir * (TT * G4 * BB);
    uint* hb = d_hbufh + dir * (2 * NBD * 128);
    unsigned* flg = &d_flagsp[dir][0][0];   // stride 32 u32 per producer

    // loader assignment: 2 threads per foreign slice
    int ls2 = tid >> 1, lhalf = tid & 1;
    int lslice = ls2 + (ls2 >= sl ? 1 : 0);
    bool loader = (tid < 2 * (NBD - 1));

    // gx offsets (gates i,f,g,o) for this thread's unit/batch-pair
    size_t goff[4];
    #pragma unroll
    for (int q = 0; q < 4; ++q)
        goff[q] = ((size_t)(q * HH + j0 + u)) * BB + b0;

    for (int st = 0; st < TT; ++st) {
        int t = dir ? (TT - 1 - st) : st;
        int p = st & 1;
        const float* Gt = G + (size_t)t * G4 * BB;

        // prefetch gx (h-independent) to overlap the flag wait
        float2 xg[4];
        #pragma unroll
        for (int q = 0; q < 4; ++q) xg[q] = *(const float2*)(Gt + goff[q]);

        // own slice: k-pair pack with partner unit (lane^4), even-u stores
        {
            uint ppk = __shfl_xor_sync(~0u, pk, 4);
            if ((u & 1) == 0) {
                uint olo = __byte_perm(pk, ppk, 0x5410);   // col b0
                uint ohi = __byte_perm(pk, ppk, 0x7632);   // col b0+1
                *(uint2*)&hsh2[(2 * sl + (u >> 1)) * 72 + b0] = make_uint2(olo, ohi);
            }
        }

        // foreign slices: poll producer flag, load bf16 slice, PRMT k-repack
        if (loader) {
            unsigned v;
            const unsigned* fp = flg + lslice * 32;
            do {
                asm volatile("ld.acquire.gpu.u32 %0, [%1];" : "=r"(v) : "l"(fp));
            } while (v < (unsigned)st);
            const uint4* src = (const uint4*)(hb + p * (NBD * 128) + lslice * 128);
            int r0 = 2 * lslice;
            #pragma unroll
            for (int g = 0; g < 4; ++g) {
                int co = lhalf * 4 + g;          // chunk-in-unit (batch group)
                int base = co * 8;               // batch base (col)
                uint4 A0 = __ldcg(src + 0 * 8 + co);   // u0
                uint4 A1 = __ldcg(src + 1 * 8 + co);   // u1
                uint4 A2 = __ldcg(src + 2 * 8 + co);   // u2
                uint4 A3 = __ldcg(src + 3 * 8 + co);   // u3
                uint4 o;
                o.x = __byte_perm(A0.x, A1.x, 0x5410);
                o.y = __byte_perm(A0.x, A1.x, 0x7632);
                o.z = __byte_perm(A0.y, A1.y, 0x5410);
                o.w = __byte_perm(A0.y, A1.y, 0x7632);
                *(uint4*)&hsh2[r0 * 72 + base] = o;
                o.x = __byte_perm(A0.z, A1.z, 0x5410);
                o.y = __byte_perm(A0.z, A1.z, 0x7632);
                o.z = __byte_perm(A0.w, A1.w, 0x5410);
                o.w = __byte_perm(A0.w, A1.w, 0x7632);
                *(uint4*)&hsh2[r0 * 72 + base + 4] = o;
                o.x = __byte_perm(A2.x, A3.x, 0x5410);
                o.y = __byte_perm(A2.x, A3.x, 0x7632);
                o.z = __byte_perm(A2.y, A3.y, 0x5410);
                o.w = __byte_perm(A2.y, A3.y, 0x7632);
                *(uint4*)&hsh2[(r0 + 1) * 72 + base] = o;
                o.x = __byte_perm(A2.z, A3.z, 0x5410);
                o.y = __byte_perm(A2.z, A3.z, 0x7632);
                o.z = __byte_perm(A2.w, A3.w, 0x5410);
                o.w = __byte_perm(A2.w, A3.w, 0x7632);
                *(uint4*)&hsh2[(r0 + 1) * 72 + base + 4] = o;
            }
        }
        __syncthreads();

        // gates(16 x 64) = W @ h  via 2 n-tiles x 13 k16-tiles of m16n8k16
        float acc0[4] = {0.f, 0.f, 0.f, 0.f};
        float acc1[4] = {0.f, 0.f, 0.f, 0.f};
        #pragma unroll
        for (int kt = 0; kt < KT3; ++kt) {
            const uint* hk = hsh2 + (kt * 8 + ctid) * 72;
            uint b00 = hk[bnw + gid];
            uint b01 = hk[4 * 72 + bnw + gid];
            uint b10 = hk[bnw + 8 + gid];
            uint b11 = hk[4 * 72 + bnw + 8 + gid];
            MMA_BF16(acc0, aw[kt], b00, b01);
            MMA_BF16(acc1, aw[kt], b10, b11);
        }

        // exchange gate pairs with partner (lane ^ 16)
        float s0 = q1 ? acc0[0] : acc1[0];
        float s1 = q1 ? acc0[1] : acc1[1];
        float s2 = q1 ? acc0[2] : acc1[2];
        float s3 = q1 ? acc0[3] : acc1[3];
        float o0 = __shfl_xor_sync(~0u, s0, 16);
        float o1 = __shfl_xor_sync(~0u, s1, 16);
        float o2 = __shfl_xor_sync(~0u, s2, 16);
        float o3 = __shfl_xor_sync(~0u, s3, 16);
        float m0 = q1 ? acc1[0] : acc0[0];
        float m1 = q1 ? acc1[1] : acc0[1];
        float m2 = q1 ? acc1[2] : acc0[2];
        float m3 = q1 ? acc1[3] : acc0[3];
        float gi0 = q1 ? o0 : m0,  gf0 = q1 ? m0 : o0;
        float gg0 = q1 ? o2 : m2,  go0 = q1 ? m2 : o2;
        float gi1 = q1 ? o1 : m1,  gf1 = q1 ? m1 : o1;
        float gg1 = q1 ? o3 : m3,  go1 = q1 ? m3 : o3;

        // activations + packed-sequence masking
        {
            float cn = sigf(gf0 + xg[1].x) * c0
                     + sigf(gi0 + xg[0].x) * tanhfast(gg0 + xg[2].x);
            float hn = sigf(go0 + xg[3].x) * tanhfast(cn);
            bool valid = (t < len0);
            hp0 = valid ? hn : hp0;
            c0  = valid ? cn : c0;
        }
        {
            float cn = sigf(gf1 + xg[1].y) * c1
                     + sigf(gi1 + xg[0].y) * tanhfast(gg1 + xg[2].y);
            float hn = sigf(go1 + xg[3].y) * tanhfast(cn);
            bool valid = (t < len1);
            hp1 = valid ? hn : hp1;
            c1  = valid ? cn : c1;
        }

        // pack bf16x2 broadcast (all blocks see the same rounded bits)
        pk = pkbf(hp0, hp1);
        __stcg(hb + (p ^ 1) * (NBD * 128) + sl * 128 + u * 32 + (b0 >> 1), pk);

        // stage full-precision h for d_hall (flushed every 4 steps)
        hstage[((st & 3) * 64 + b0) * 4 + u] = hp0;
        hstage[((st & 3) * 64 + b0 + 1) * 4 + u] = hp1;

        __syncthreads();
        if (tid == 0) {
            asm volatile("fence.acq_rel.gpu;" ::: "memory");
            asm volatile("st.relaxed.gpu.u32 [%0], %1;"
                         :: "l"(flg + sl * 32), "r"((unsigned)(st + 1)) : "memory");
        }

        // coalesced d_hall flush, off the critical path
        if ((st & 3) == 3) {
            #pragma unroll
            for (int rep = 0; rep < 2; ++rep) {
                int idx = tid + rep * 128;
                int tf = idx >> 6, b = idx & 63;
                float4 hv = *(const float4*)&hstage[(tf * 64 + b) * 4];
                int tt = dir ? (TT - 1 - (st - 3 + tf)) : (st - 3 + tf);
                *(float4*)&d_hall[((size_t)tt * BB + b) * (2 * HH) + dir * HH + j0] = hv;
            }
        }
    }
}

// ---------------- K4: FC + log_softmax (warp per token) ----------------
__global__ void __launch_bounds__(128) k4_fc(
    const float* __restrict__ fcw, const float* __restrict__ fcb)
{
    __shared__ float wsh[CC * 401];
    __shared__ float fbsh[CC];
    __shared__ float hs4[4][2 * HH];
    int tid = threadIdx.x;
    for (int i = tid; i < CC * 2 * HH; i += 128) {
        int c = i / (2 * HH), k = i % (2 * HH);
        wsh[c * 401 + k] = fcw[i];
    }
    if (tid < CC) fbsh[tid] = fcb[tid];
    __syncthreads();

    int w = tid >> 5, lane = tid & 31;
    int tok = blockIdx.x * 4 + w;                    // tok = t*64 + b
    for (int k = lane; k < 2 * HH; k += 32) hs4[w][k] = d_hall[(size_t)tok * (2 * HH) + k];
    __syncwarp();

    float acc = -1e30f;
    if (lane < CC) {
        acc = fbsh[lane];
        const float* wr = wsh + lane * 401;
        #pragma unroll 4
        for (int k = 0; k < 2 * HH; ++k) acc += hs4[w][k] * wr[k];
    }
    float m = acc;
    #pragma unroll
    for (int o = 16; o; o >>= 1) m = fmaxf(m, __shfl_xor_sync(~0u, m, o));
    float e = (lane < CC) ? __expf(acc - m) : 0.f;
    #pragma unroll
    for (int o = 16; o; o >>= 1) e += __shfl_xor_sync(~0u, e, o);
    float lse = m + __logf(e);
    if (lane < CC) {
        int t = tok >> 6, b = tok & 63;
        d_logits[((size_t)b * TT + t) * CC + lane] = acc - lse;
    }
}

// ---------------- K5: CRF NLL, one warp per batch element ----------------
__global__ void __launch_bounds__(32) k5_crf(
    const int* __restrict__ seq_len, const int* __restrict__ target,
    const float* __restrict__ trans, const float* __restrict__ start,
    const float* __restrict__ endsc)
{
    int b = blockIdx.x;
    int lane = threadIdx.x;
    int c = (lane < CC) ? lane : 0;
    int len = seq_len[b];
    const float* L = d_logits + (size_t)b * TT * CC;
    const int* tg = target + (size_t)b * TT;

    float tcol[CC];
    #pragma unroll
    for (int i = 0; i < CC; ++i) tcol[i] = (lane < CC) ? trans[i * CC + c] : 0.f;

    float alpha = (lane < CC) ? (start[c] + L[c]) : -1e30f;

    for (int t = 1; t < len; ++t) {
        float va[CC];
        #pragma unroll
        for (int i = 0; i < CC; ++i)
            va[i] = __shfl_sync(~0u, alpha, i) + tcol[i];
        float m = va[0];
        #pragma unroll
        for (int i = 1; i < CC; ++i) m = fmaxf(m, va[i]);
        float s = 0.f;
        #pragma unroll
        for (int i = 0; i < CC; ++i) s += __expf(va[i] - m);
        float emit = (lane < CC) ? L[t * CC + c] : 0.f;
        float nw = m + __logf(s) + emit;
        alpha = (lane < CC) ? nw : -1e30f;
    }

    float v = (lane < CC) ? (alpha + endsc[c]) : -1e30f;
    float m = v;
    #pragma unroll
    for (int o = 16; o; o >>= 1) m = fmaxf(m, __shfl_xor_sync(~0u, m, o));
    float s = __expf(v - m);
    if (lane >= CC) s = 0.f;
    #pragma unroll
    for (int o = 16; o; o >>= 1) s += __shfl_xor_sync(~0u, s, o);
    float logZ = m + __logf(s);

    float es = 0.f;
    for (int t = lane; t < len; t += 32) es += L[t * CC + tg[t]];
    float ts = 0.f;
    for (int t = lane; t < len - 1; t += 32) ts += trans[tg[t] * CC + tg[t + 1]];
    float g = es + ts;
    #pragma unroll
    for (int o = 16; o; o >>= 1) g += __shfl_xor_sync(~0u, g, o);
    if (lane == 0) {
        float gold = g + start[tg[0]] + endsc[tg[len - 1]];
        d_loss[b] = logZ - gold;
    }
}

// ---------------- K6: mean reduce ----------------
__global__ void __launch_bounds__(64) k6_mean(float* out) {
    __shared__ float sh[64];
    int tid = threadIdx.x;
    sh[tid] = d_loss[tid];
    __syncthreads();
    for (int o = 32; o; o >>= 1) {
        if (tid < o) sh[tid] += sh[tid + o];
        __syncthreads();
    }
    if (tid == 0) out[0] = sh[0] * (1.f / BB);
}

// ---------------- launch ----------------
extern "C" void kernel_launch(void* const* d_in, const int* in_sizes, int n_in,
                              void* d_out, int out_size) {
    const int*   words   = (const int*)d_in[0];
    const int*   seq_len = (const int*)d_in[1];
    const int*   target  = (const int*)d_in[2];
    const float* embed   = (const float*)d_in[3];
    const float* gamma   = (const float*)d_in[4];
    const float* beta    = (const float*)d_in[5];
    const float* wihf    = (const float*)d_in[6];
    const float* whhf    = (const float*)d_in[7];
    const float* bf      = (const float*)d_in[8];
    const float* wihb    = (const float*)d_in[9];
    const float* whhb    = (const float*)d_in[10];
    const float* bb      = (const float*)d_in[11];
    const float* fcw     = (const float*)d_in[12];
    const float* fcb     = (const float*)d_in[13];
    const float* trans   = (const float*)d_in[14];
    const float* startsc = (const float*)d_in[15];
    const float* endsc   = (const float*)d_in[16];
    float* out = (float*)d_out;

    size_t hsmem = (size_t)(104 * 72) * sizeof(uint) + 4 * 64 * 4 * sizeof(float);
    cudaFuncSetAttribute(k3_lstm, cudaFuncAttributeMaxDynamicSharedMemorySize,
                         (int)hsmem);

    k0_init<<<1, 256>>>();
    k1_embed_ln<<<TT * BB / 8, 256>>>(words, embed, gamma, beta);
    {
        dim3 g(2 * G4 / 64, TT * BB / 128);   // 25 x 256
        k2_gemm<<<g, 256>>>(wihf, wihb, bf, bb);
    }
    k3_lstm<<<2 * NBD, 128, hsmem>>>(whhf, whhb, seq_len);
    k4_fc<<<TT * BB / 4, 128>>>(fcw, fcb);
    k5_crf<<<BB, 32>>>(seq_len, target, trans, startsc, endsc);
    k6_mean<<<1, 64>>>(out);
}

// round 9
// speedup vs baseline: 2.3094x; 1.0405x over previous
#include <cuda_runtime.h>
#include <cuda_bf16.h>
#include <math.h>

#define TT 512
#define BB 64
#define EE 256
#define HH 200
#define G4 800
#define CC 20
#define NBD 50   // blocks per direction in LSTM kernel
#define HSL 4    // h-units per block (HH / NBD)
#define KT3 13   // k16-tiles covering HH=200 (pad to 208)

typedef unsigned int uint;

// ---------------- device scratch (no allocations allowed) ----------------
__device__ uint  d_xh[TT * BB * (EE / 2)];        // LN'd embeddings bf16x2, 16.8MB
__device__ uint  d_Gh[2 * TT * G4 * 32];          // gates_x bf16x2 (batch pairs), 105MB
__device__ uint  d_hallh[2 * (TT + 1) * NBD * 128]; // h history bf16x2 [dir][slot][sl][u*32+bp]
__device__ float d_logits[BB * TT * CC];          // log_softmax outputs [b][t][c]
__device__ float d_loss[BB];
__device__ unsigned d_flagsp[2][NBD][32];         // flags spread 128B apart

#define HSLOT 6400           // uints per history slot (NBD*128)
#define HDIR  ((TT + 1) * HSLOT)

__device__ __forceinline__ uint pkbf(float lo, float hi) {
    uint r;
    asm("cvt.rn.bf16x2.f32 %0, %1, %2;" : "=r"(r) : "f"(hi), "f"(lo));
    return r;
}
__device__ __forceinline__ float bflo(uint v) { return __uint_as_float(v << 16); }
__device__ __forceinline__ float bfhi(uint v) { return __uint_as_float(v & 0xffff0000u); }
__device__ __forceinline__ float sigf(float x)  { return 1.f / (1.f + __expf(-x)); }
__device__ __forceinline__ float tanhfast(float x) { return 1.f - 2.f / (__expf(2.f * x) + 1.f); }

#define MMA_BF16(ACC, A, B0, B1)                                           \
    asm volatile(                                                          \
        "mma.sync.aligned.m16n8k16.row.col.f32.bf16.bf16.f32 "             \
        "{%0,%1,%2,%3}, {%4,%5,%6,%7}, {%8,%9}, {%0,%1,%2,%3};"            \
        : "+f"((ACC)[0]), "+f"((ACC)[1]), "+f"((ACC)[2]), "+f"((ACC)[3])   \
        : "r"((A)[0]), "r"((A)[1]), "r"((A)[2]), "r"((A)[3]),              \
          "r"(B0), "r"(B1))

// ---------------- K0: init (zero boundary h slots + flags) ----------------
__global__ void k0_init() {
    int tid = threadIdx.x;
    for (int i = tid; i < HSLOT; i += 256) {
        d_hallh[i] = 0u;                          // dir0, slot 0
        d_hallh[HDIR + (size_t)TT * HSLOT + i] = 0u;  // dir1, slot TT
    }
    for (int i = tid; i < 2 * NBD * 32; i += 256) ((unsigned*)d_flagsp)[i] = 0u;
}

// ---------------- K1: embedding + LayerNorm -> bf16x2 (warp per token) ----------------
__global__ void __launch_bounds__(256) k1_embed_ln(
    const int* __restrict__ words, const float* __restrict__ embed,
    const float* __restrict__ gamma, const float* __restrict__ beta)
{
    int wid = threadIdx.x >> 5, lane = threadIdx.x & 31;
    int tok = blockIdx.x * 8 + wid;          // tok = t*64 + b
    int t = tok >> 6, b = tok & 63;
    int word = words[b * TT + t];
    const float4* src = (const float4*)(embed + (size_t)word * EE);
    float4 v0 = src[lane * 2], v1 = src[lane * 2 + 1];
    float s = v0.x + v0.y + v0.z + v0.w + v1.x + v1.y + v1.z + v1.w;
    float q = v0.x*v0.x + v0.y*v0.y + v0.z*v0.z + v0.w*v0.w
            + v1.x*v1.x + v1.y*v1.y + v1.z*v1.z + v1.w*v1.w;
    #pragma unroll
    for (int o = 16; o; o >>= 1) {
        s += __shfl_xor_sync(~0u, s, o);
        q += __shfl_xor_sync(~0u, q, o);
    }
    float mu  = s * (1.f / EE);
    float var = q * (1.f / EE) - mu * mu;
    float rs  = rsqrtf(var + 1e-5f);
    const float4* g4 = (const float4*)gamma;
    const float4* bt4 = (const float4*)beta;
    float4 ga = g4[lane*2], gb = g4[lane*2+1];
    float4 ba = bt4[lane*2], bb = bt4[lane*2+1];
    float o0x = (v0.x-mu)*rs*ga.x + ba.x,  o0y = (v0.y-mu)*rs*ga.y + ba.y;
    float o0z = (v0.z-mu)*rs*ga.z + ba.z,  o0w = (v0.w-mu)*rs*ga.w + ba.w;
    float o1x = (v1.x-mu)*rs*gb.x + bb.x,  o1y = (v1.y-mu)*rs*gb.y + bb.y;
    float o1z = (v1.z-mu)*rs*gb.z + bb.z,  o1w = (v1.w-mu)*rs*gb.w + bb.w;
    uint4 pk;
    pk.x = pkbf(o0x, o0y);  pk.y = pkbf(o0z, o0w);
    pk.z = pkbf(o1x, o1y);  pk.w = pkbf(o1z, o1w);
    *(uint4*)(d_xh + (size_t)tok * 128 + lane * 4) = pk;
}

// ---------------- K2: bf16 tensor-core GEMM  gates_x = X @ W_ih^T + b ----------------
// C[32768,1600]. BM=128, BN=64, BK=16, 8 warps (4m x 2n), m16n8k16 bf16.
// Output packed bf16x2 over adjacent-batch pairs into d_Gh.
__global__ void __launch_bounds__(256) k2_gemm(
    const float* __restrict__ wihf, const float* __restrict__ wihb,
    const float* __restrict__ bf,   const float* __restrict__ bbias)
{
    __shared__ uint As2[128 * 12];   // [m][k/2] bf16x2, stride 12 (8 data + 4 pad)
    __shared__ uint Bs2[64 * 12];

    int tid = threadIdx.x;
    int m0 = blockIdx.y * 128, n0 = blockIdx.x * 64;
    int wid = tid >> 5, lane = tid & 31;
    int wm = wid & 3, wn = wid >> 2;            // warp grid 4 x 2
    int gid = lane >> 2, ctid = lane & 3;

    float acc[2][4][4];
    #pragma unroll
    for (int mi = 0; mi < 2; ++mi)
        #pragma unroll
        for (int ni = 0; ni < 4; ++ni)
            #pragma unroll
            for (int r = 0; r < 4; ++r) acc[mi][ni][r] = 0.f;

    for (int k0 = 0; k0 < EE; k0 += 16) {
        // A tile: 128 rows x 8 bf16x2 — direct uint4 copy from d_xh
        {
            int row = tid >> 1, part = tid & 1;
            uint4 v = *(const uint4*)(d_xh + (size_t)(m0 + row) * 128 + (k0 >> 1) + part * 4);
            uint* dst = As2 + row * 12 + part * 4;
            dst[0] = v.x; dst[1] = v.y; dst[2] = v.z; dst[3] = v.w;
        }
        // B tile: 64x16 fp32 -> bf16x2
        {
            int row = tid >> 2, kq = (tid & 3) * 4;
            int nglob = n0 + row;
            const float* wrow = (nglob < G4) ? (wihf + (size_t)nglob * EE)
                                             : (wihb + (size_t)(nglob - G4) * EE);
            float4 v = *(const float4*)(wrow + k0 + kq);
            uint* dst = Bs2 + row * 12 + (tid & 3) * 2;
            dst[0] = pkbf(v.x, v.y);
            dst[1] = pkbf(v.z, v.w);
        }
        __syncthreads();

        uint afr[2][4], bfr[4][2];
        #pragma unroll
        for (int mi = 0; mi < 2; ++mi) {
            int mb = wm * 32 + mi * 16;
            const uint* ap = As2 + (mb + gid) * 12 + ctid;
            afr[mi][0] = ap[0];
            afr[mi][1] = ap[8 * 12];
            afr[mi][2] = ap[4];
            afr[mi][3] = ap[8 * 12 + 4];
        }
        #pragma unroll
        for (int ni = 0; ni < 4; ++ni) {
            int nb = wn * 32 + ni * 8;
            const uint* bp = Bs2 + (nb + gid) * 12 + ctid;
            bfr[ni][0] = bp[0];
            bfr[ni][1] = bp[4];
        }
        #pragma unroll
        for (int mi = 0; mi < 2; ++mi)
            #pragma unroll
            for (int ni = 0; ni < 4; ++ni)
                MMA_BF16(acc[mi][ni], afr[mi], bfr[ni][0], bfr[ni][1]);
        __syncthreads();
    }

    // epilogue: add bias, pack adjacent-batch pairs (lanes gid even/odd), store bf16x2
    #pragma unroll
    for (int mi = 0; mi < 2; ++mi)
        #pragma unroll
        for (int ni = 0; ni < 4; ++ni)
            #pragma unroll
            for (int r = 0; r < 4; ++r) {
                int n = n0 + wn * 32 + ni * 8 + 2 * ctid + (r & 1);
                int dir = (n >= G4) ? 1 : 0;
                int rr = n - dir * G4;
                float val = acc[mi][ni][r] + (dir ? bbias[rr] : bf[rr]);
                float pv = __shfl_xor_sync(~0u, val, 4);   // partner batch b+1
                if ((gid & 1) == 0) {
                    int m = m0 + wm * 32 + mi * 16 + gid + (r >> 1) * 8;
                    int t = m >> 6, b = m & 63;            // b even
                    d_Gh[((size_t)dir * TT * G4 + (size_t)t * G4 + rr) * 32 + (b >> 1)]
                        = pkbf(val, pv);
                }
            }
}

// ---------------- K3: persistent BiLSTM, bf16 tensor-core recurrence ----------------
// h exchanged via t-indexed bf16 history (no reuse, no d_hall flush);
// gx prefetched one full step ahead (DRAM latency off the critical path).
__global__ void __launch_bounds__(128, 1) k3_lstm(
    const float* __restrict__ whhf, const float* __restrict__ whhb,
    const int* __restrict__ seq_len)
{
    extern __shared__ uint hsh2[];            // [104][72] bf16x2 (k-pair, n) 29952 B

    int tid = threadIdx.x;
    int dir = blockIdx.x / NBD;
    int sl  = blockIdx.x % NBD;
    int j0  = sl * HSL;
    const float* whh = dir ? whhb : whhf;

    int wid = tid >> 5, lane = tid & 31;
    int gid = lane >> 2, ctid = lane & 3;
    int u   = gid & 3;            // local hidden unit 0..3
    int q1  = gid >> 2;           // 0: rows {i,g}; 1: rows {f,o}
    int bnw = wid * 16;           // warp batch base
    int b0  = bnw + q1 * 8 + 2 * ctid;   // this thread's batch pair (b0, b0+1)

    // persistent bf16 A fragments (k16 tiles; zero-pad k>=200)
    uint aw[KT3][4];
    {
        int rowA = q1 * HH + j0 + u;         // mma row gid   -> gate q1
        int rowB = (q1 + 2) * HH + j0 + u;   // mma row gid+8 -> gate q1+2
        #pragma unroll
        for (int kt = 0; kt < KT3; ++kt) {
            int kA = kt * 16 + 2 * ctid;
            int kC = kA + 8;
            float a0 = whh[(size_t)rowA * HH + kA];
            float a1 = whh[(size_t)rowA * HH + kA + 1];
            float b0v = whh[(size_t)rowB * HH + kA];
            float b1v = whh[(size_t)rowB * HH + kA + 1];
            float a2 = (kC < HH) ? whh[(size_t)rowA * HH + kC] : 0.f;
            float a3 = (kC + 1 < HH) ? whh[(size_t)rowA * HH + kC + 1] : 0.f;
            float b2v = (kC < HH) ? whh[(size_t)rowB * HH + kC] : 0.f;
            float b3v = (kC + 1 < HH) ? whh[(size_t)rowB * HH + kC + 1] : 0.f;
            aw[kt][0] = pkbf(a0, a1);
            aw[kt][1] = pkbf(b0v, b1v);
            aw[kt][2] = pkbf(a2, a3);
            aw[kt][3] = pkbf(b2v, b3v);
        }
    }

    // zero the pad rows 100..103 (k 200..207) once
    for (int i = tid; i < 4 * 72; i += 128) hsh2[100 * 72 + i] = 0u;

    int len0 = seq_len[b0], len1 = seq_len[b0 + 1];
    float c0 = 0.f, c1 = 0.f, hp0 = 0.f, hp1 = 0.f;
    uint pk = 0u;                 // packed bf16x2 (hp0 lo, hp1 hi)

    uint* hbase = d_hallh + (size_t)dir * HDIR;
    unsigned* flg = &d_flagsp[dir][0][0];   // stride 32 u32 per producer

    // loader assignment: 2 threads per foreign slice
    int ls2 = tid >> 1, lhalf = tid & 1;
    int lslice = ls2 + (ls2 >= sl ? 1 : 0);
    bool loader = (tid < 2 * (NBD - 1));

    // gx offsets (gates i,f,g,o), uint units within a t-slab of G4*32
    int goff[4];
    #pragma unroll
    for (int q = 0; q < 4; ++q)
        goff[q] = (q * HH + j0 + u) * 32 + (b0 >> 1);

    const uint* Gd = d_Gh + (size_t)dir * TT * G4 * 32;

    // preload gx for st=0
    uint xg[4];
    {
        int t0 = dir ? (TT - 1) : 0;
        const uint* Gt = Gd + (size_t)t0 * G4 * 32;
        #pragma unroll
        for (int q = 0; q < 4; ++q) xg[q] = __ldcg(Gt + goff[q]);
    }

    for (int st = 0; st < TT; ++st) {
        int t = dir ? (TT - 1 - st) : st;
        int rs = dir ? (t + 1) : t;        // read slot (h of previous step)
        int ws = dir ? t : (t + 1);        // write slot (h of this step)

        // own slice: k-pair pack with partner unit (lane^4), even-u stores
        {
            uint ppk = __shfl_xor_sync(~0u, pk, 4);
            if ((u & 1) == 0) {
                uint olo = __byte_perm(pk, ppk, 0x5410);   // col b0
                uint ohi = __byte_perm(pk, ppk, 0x7632);   // col b0+1
                *(uint2*)&hsh2[(2 * sl + (u >> 1)) * 72 + b0] = make_uint2(olo, ohi);
            }
        }

        // foreign slices: poll producer flag, load bf16 slice, PRMT k-repack
        if (loader) {
            unsigned v;
            const unsigned* fp = flg + lslice * 32;
            do {
                asm volatile("ld.acquire.gpu.u32 %0, [%1];" : "=r"(v) : "l"(fp));
            } while (v < (unsigned)st);
            const uint4* src = (const uint4*)(hbase + (size_t)rs * HSLOT + lslice * 128);
            int r0 = 2 * lslice;
            #pragma unroll
            for (int g = 0; g < 4; ++g) {
                int co = lhalf * 4 + g;          // chunk-in-unit (batch group)
                int base = co * 8;               // batch base (col)
                uint4 A0 = __ldcg(src + 0 * 8 + co);   // u0
                uint4 A1 = __ldcg(src + 1 * 8 + co);   // u1
                uint4 A2 = __ldcg(src + 2 * 8 + co);   // u2
                uint4 A3 = __ldcg(src + 3 * 8 + co);   // u3
                uint4 o;
                o.x = __byte_perm(A0.x, A1.x, 0x5410);
                o.y = __byte_perm(A0.x, A1.x, 0x7632);
                o.z = __byte_perm(A0.y, A1.y, 0x5410);
                o.w = __byte_perm(A0.y, A1.y, 0x7632);
                *(uint4*)&hsh2[r0 * 72 + base] = o;
                o.x = __byte_perm(A0.z, A1.z, 0x5410);
                o.y = __byte_perm(A0.z, A1.z, 0x7632);
                o.z = __byte_perm(A0.w, A1.w, 0x5410);
                o.w = __byte_perm(A0.w, A1.w, 0x7632);
                *(uint4*)&hsh2[r0 * 72 + base + 4] = o;
                o.x = __byte_perm(A2.x, A3.x, 0x5410);
                o.y = __byte_perm(A2.x, A3.x, 0x7632);
                o.z = __byte_perm(A2.y, A3.y, 0x5410);
                o.w = __byte_perm(A2.y, A3.y, 0x7632);
                *(uint4*)&hsh2[(r0 + 1) * 72 + base] = o;
                o.x = __byte_perm(A2.z, A3.z, 0x5410);
                o.y = __byte_perm(A2.z, A3.z, 0x7632);
                o.z = __byte_perm(A2.w, A3.w, 0x5410);
                o.w = __byte_perm(A2.w, A3.w, 0x7632);
                *(uint4*)&hsh2[(r0 + 1) * 72 + base + 4] = o;
            }
        }
        __syncthreads();

        // gates(16 x 64) = W @ h  via 2 n-tiles x 13 k16-tiles of m16n8k16
        float acc0[4] = {0.f, 0.f, 0.f, 0.f};
        float acc1[4] = {0.f, 0.f, 0.f, 0.f};
        #pragma unroll
        for (int kt = 0; kt < KT3; ++kt) {
            const uint* hk = hsh2 + (kt * 8 + ctid) * 72;
            uint b00 = hk[bnw + gid];
            uint b01 = hk[4 * 72 + bnw + gid];
            uint b10 = hk[bnw + 8 + gid];
            uint b11 = hk[4 * 72 + bnw + 8 + gid];
            MMA_BF16(acc0, aw[kt], b00, b01);
            MMA_BF16(acc1, aw[kt], b10, b11);
        }

        // exchange gate pairs with partner (lane ^ 16)
        float s0 = q1 ? acc0[0] : acc1[0];
        float s1 = q1 ? acc0[1] : acc1[1];
        float s2 = q1 ? acc0[2] : acc1[2];
        float s3 = q1 ? acc0[3] : acc1[3];
        float o0 = __shfl_xor_sync(~0u, s0, 16);
        float o1 = __shfl_xor_sync(~0u, s1, 16);
        float o2 = __shfl_xor_sync(~0u, s2, 16);
        float o3 = __shfl_xor_sync(~0u, s3, 16);
        float m0 = q1 ? acc1[0] : acc0[0];
        float m1 = q1 ? acc1[1] : acc0[1];
        float m2 = q1 ? acc1[2] : acc0[2];
        float m3 = q1 ? acc1[3] : acc0[3];
        float gi0 = q1 ? o0 : m0,  gf0 = q1 ? m0 : o0;
        float gg0 = q1 ? o2 : m2,  go0 = q1 ? m2 : o2;
        float gi1 = q1 ? o1 : m1,  gf1 = q1 ? m1 : o1;
        float gg1 = q1 ? o3 : m3,  go1 = q1 ? m3 : o3;

        // activations + packed-sequence masking (gx from prefetched bf16x2)
        {
            float cn = sigf(gf0 + bflo(xg[1])) * c0
                     + sigf(gi0 + bflo(xg[0])) * tanhfast(gg0 + bflo(xg[2]));
            float hn = sigf(go0 + bflo(xg[3])) * tanhfast(cn);
            bool valid = (t < len0);
            hp0 = valid ? hn : hp0;
            c0  = valid ? cn : c0;
        }
        {
            float cn = sigf(gf1 + bfhi(xg[1])) * c1
                     + sigf(gi1 + bfhi(xg[0])) * tanhfast(gg1 + bfhi(xg[2]));
            float hn = sigf(go1 + bfhi(xg[3])) * tanhfast(cn);
            bool valid = (t < len1);
            hp1 = valid ? hn : hp1;
            c1  = valid ? cn : c1;
        }

        // broadcast rounded h into the history (this IS the record for k4 too)
        pk = pkbf(hp0, hp1);
        __stcg(hbase + (size_t)ws * HSLOT + sl * 128 + u * 32 + (b0 >> 1), pk);

        __syncthreads();
        if (tid == 0) {
            asm volatile("fence.acq_rel.gpu;" ::: "memory");
            asm volatile("st.relaxed.gpu.u32 [%0], %1;"
                         :: "l"(flg + sl * 32), "r"((unsigned)(st + 1)) : "memory");
        }

        // prefetch next step's gx (off the critical path: ~a full step of slack)
        if (st + 1 < TT) {
            int tn = dir ? (TT - 2 - st) : (st + 1);
            const uint* Gt = Gd + (size_t)tn * G4 * 32;
            #pragma unroll
            for (int q = 0; q < 4; ++q) xg[q] = __ldcg(Gt + goff[q]);
        }
    }
}

// ---------------- K4: FC + log_softmax (block = 16 tokens of one t) ----------------
__global__ void __launch_bounds__(128) k4_fc(
    const float* __restrict__ fcw, const float* __restrict__ fcb)
{
    __shared__ float wsh[CC * 402];    // pad 402 (even) for float2 column reads
    __shared__ float fbsh[CC];
    __shared__ uint  hs[8][400];       // [local bpair][feature]
    int tid = threadIdx.x;
    int bid = blockIdx.x;
    int t = bid >> 2, bg = bid & 3, b0 = bg * 16;

    for (int i = tid; i < CC * 400; i += 128) {
        int c = i / 400, j = i % 400;
        wsh[c * 402 + j] = fcw[i];
    }
    if (tid < CC) fbsh[tid] = fcb[tid];

    // stage h: 400 features x 8 bpairs from the bf16 history
    for (int c = tid; c < 1600; c += 128) {
        int row = c >> 2, part = c & 3;
        int dir = (row >= 200) ? 1 : 0;
        int jj = row - dir * 200;
        size_t slot = dir ? (size_t)t : (size_t)(t + 1);
        size_t addr = (size_t)dir * HDIR + slot * HSLOT
                    + (jj >> 2) * 128 + (jj & 3) * 32 + (b0 >> 1) + part * 2;
        uint2 v = *(const uint2*)&d_hallh[addr];
        hs[part * 2][row] = v.x;
        hs[part * 2 + 1][row] = v.y;
    }
    __syncthreads();

    int w = tid >> 5, lane = tid & 31;
    #pragma unroll
    for (int tk = 0; tk < 4; ++tk) {
        int bloc = w * 4 + tk;
        const uint* hrow = hs[bloc >> 1];
        int half = bloc & 1;
        float acc = -1e30f;
        if (lane < CC) {
            acc = fbsh[lane];
            const float* wr = wsh + lane * 402;
            #pragma unroll 4
            for (int j = 0; j < 400; j += 2) {
                uint2 hv = *(const uint2*)&hrow[j];
                float h0 = half ? bfhi(hv.x) : bflo(hv.x);
                float h1 = half ? bfhi(hv.y) : bflo(hv.y);
                float2 wv = *(const float2*)&wr[j];
                acc += h0 * wv.x + h1 * wv.y;
            }
        }
        float m = acc;
        #pragma unroll
        for (int o = 16; o; o >>= 1) m = fmaxf(m, __shfl_xor_sync(~0u, m, o));
        float e = (lane < CC) ? __expf(acc - m) : 0.f;
        #pragma unroll
        for (int o = 16; o; o >>= 1) e += __shfl_xor_sync(~0u, e, o);
        float lse = m + __logf(e);
        if (lane < CC) {
            int b = b0 + bloc;
            d_logits[((size_t)b * TT + t) * CC + lane] = acc - lse;
        }
    }
}

// ---------------- K5: CRF NLL, one warp per batch element ----------------
__global__ void __launch_bounds__(32) k5_crf(
    const int* __restrict__ seq_len, const int* __restrict__ target,
    const float* __restrict__ trans, const float* __restrict__ start,
    const float* __restrict__ endsc)
{
    int b = blockIdx.x;
    int lane = threadIdx.x;
    int c = (lane < CC) ? lane : 0;
    int len = seq_len[b];
    const float* L = d_logits + (size_t)b * TT * CC;
    const int* tg = target + (size_t)b * TT;

    float tcol[CC];
    #pragma unroll
    for (int i = 0; i < CC; ++i) tcol[i] = (lane < CC) ? trans[i * CC + c] : 0.f;

    float alpha = (lane < CC) ? (start[c] + L[c]) : -1e30f;

    for (int t = 1; t < len; ++t) {
        float va[CC];
        #pragma unroll
        for (int i = 0; i < CC; ++i)
            va[i] = __shfl_sync(~0u, alpha, i) + tcol[i];
        float m = va[0];
        #pragma unroll
        for (int i = 1; i < CC; ++i) m = fmaxf(m, va[i]);
        float s = 0.f;
        #pragma unroll
        for (int i = 0; i < CC; ++i) s += __expf(va[i] - m);
        float emit = (lane < CC) ? L[t * CC + c] : 0.f;
        float nw = m + __logf(s) + emit;
        alpha = (lane < CC) ? nw : -1e30f;
    }

    float v = (lane < CC) ? (alpha + endsc[c]) : -1e30f;
    float m = v;
    #pragma unroll
    for (int o = 16; o; o >>= 1) m = fmaxf(m, __shfl_xor_sync(~0u, m, o));
    float s = __expf(v - m);
    if (lane >= CC) s = 0.f;
    #pragma unroll
    for (int o = 16; o; o >>= 1) s += __shfl_xor_sync(~0u, s, o);
    float logZ = m + __logf(s);

    float es = 0.f;
    for (int t = lane; t < len; t += 32) es += L[t * CC + tg[t]];
    float ts = 0.f;
    for (int t = lane; t < len - 1; t += 32) ts += trans[tg[t] * CC + tg[t + 1]];
    float g = es + ts;
    #pragma unroll
    for (int o = 16; o; o >>= 1) g += __shfl_xor_sync(~0u, g, o);
    if (lane == 0) {
        float gold = g + start[tg[0]] + endsc[tg[len - 1]];
        d_loss[b] = logZ - gold;
    }
}

// ---------------- K6: mean reduce ----------------
__global__ void __launch_bounds__(64) k6_mean(float* out) {
    __shared__ float sh[64];
    int tid = threadIdx.x;
    sh[tid] = d_loss[tid];
    __syncthreads();
    for (int o = 32; o; o >>= 1) {
        if (tid < o) sh[tid] += sh[tid + o];
        __syncthreads();
    }
    if (tid == 0) out[0] = sh[0] * (1.f / BB);
}

// ---------------- launch ----------------
extern "C" void kernel_launch(void* const* d_in, const int* in_sizes, int n_in,
                              void* d_out, int out_size) {
    const int*   words   = (const int*)d_in[0];
    const int*   seq_len = (const int*)d_in[1];
    const int*   target  = (const int*)d_in[2];
    const float* embed   = (const float*)d_in[3];
    const float* gamma   = (const float*)d_in[4];
    const float* beta    = (const float*)d_in[5];
    const float* wihf    = (const float*)d_in[6];
    const float* whhf    = (const float*)d_in[7];
    const float* bf      = (const float*)d_in[8];
    const float* wihb    = (const float*)d_in[9];
    const float* whhb    = (const float*)d_in[10];
    const float* bb      = (const float*)d_in[11];
    const float* fcw     = (const float*)d_in[12];
    const float* fcb     = (const float*)d_in[13];
    const float* trans   = (const float*)d_in[14];
    const float* startsc = (const float*)d_in[15];
    const float* endsc   = (const float*)d_in[16];
    float* out = (float*)d_out;

    size_t hsmem = (size_t)(104 * 72) * sizeof(uint);   // 29952 B
    cudaFuncSetAttribute(k3_lstm, cudaFuncAttributeMaxDynamicSharedMemorySize,
                         (int)hsmem);

    k0_init<<<1, 256>>>();
    k1_embed_ln<<<TT * BB / 8, 256>>>(words, embed, gamma, beta);
    {
        dim3 g(2 * G4 / 64, TT * BB / 128);   // 25 x 256
        k2_gemm<<<g, 256>>>(wihf, wihb, bf, bb);
    }
    k3_lstm<<<2 * NBD, 128, hsmem>>>(whhf, whhb, seq_len);
    k4_fc<<<TT * 4, 128>>>(fcw, fcb);
    k5_crf<<<BB, 32>>>(seq_len, target, trans, startsc, endsc);
    k6_mean<<<1, 64>>>(out);
}